// round 1
// baseline (speedup 1.0000x reference)
#include <cuda_runtime.h>
#include <math.h>

// Problem constants
#define Bb   8
#define Cc   256
#define Hh   64
#define Ww   64
#define NQ   4096           // H*W
#define NPIX (Bb*NQ)        // 32768
#define NHh  4
#define NPp  4
#define Dd   64
#define EPSf 1e-5f

// ---------------- scratch (static device globals; no allocation) ----------------
__device__ float g_mean1[NPIX], g_rstd1[NPIX], g_mean2[NPIX], g_rstd2[NPIX];
__device__ float g_qp[NQ * 48];        // qpos @ [W_off | W_att]
__device__ float g_c48[48];            // b + ln1_b @ W
__device__ float g_gs48[48];           // ln1_g @ W
__device__ float g_vG[Cc];             // ln2_g @ W_val
__device__ float g_vc[Cc];             // b_val + ln2_b @ W_val
__device__ float g_value[NPIX * Cc];   // (B, Nq, C): value after LN+W_val
__device__ float g_smp[NPIX * 48];     // per (b,q): 32 pixel-coords (px,py per h,p) + 16 softmaxed att
__device__ float g_S[NPIX * Cc];       // sampled output (B, Nq, C)

// ---------------- K0: tiny constant precompute ----------------
__global__ void k_const(const float* __restrict__ ln1_g, const float* __restrict__ ln1_b,
                        const float* __restrict__ ln2_g, const float* __restrict__ ln2_b,
                        const float* __restrict__ W_off, const float* __restrict__ b_off,
                        const float* __restrict__ W_att, const float* __restrict__ b_att,
                        const float* __restrict__ W_val, const float* __restrict__ b_val)
{
    int t = threadIdx.x;   // 256 threads
    float sG = 0.f, sc = 0.f;
    for (int k = 0; k < Cc; k++) {
        float w = W_val[k * Cc + t];
        sG += ln2_g[k] * w;
        sc += ln2_b[k] * w;
    }
    g_vG[t] = sG;
    g_vc[t] = sc + b_val[t];

    if (t < 48) {
        float s1 = 0.f, s2 = 0.f, bb;
        if (t < 32) {
            for (int k = 0; k < Cc; k++) {
                float w = W_off[k * 32 + t];
                s1 += ln1_b[k] * w;
                s2 += ln1_g[k] * w;
            }
            bb = b_off[t];
        } else {
            int j = t - 32;
            for (int k = 0; k < Cc; k++) {
                float w = W_att[k * 16 + j];
                s1 += ln1_b[k] * w;
                s2 += ln1_g[k] * w;
            }
            bb = b_att[j];
        }
        g_c48[t] = s1 + bb;
        g_gs48[t] = s2;
    }
}

// ---------------- K1: per-pixel mean / rstd for x1 and x2 ----------------
__global__ void k_stats(const float* __restrict__ x1, const float* __restrict__ x2)
{
    int t = blockIdx.x * blockDim.x + threadIdx.x;      // 0 .. 2*NPIX-1
    int idx = t & (NPIX - 1);
    const float* x = (t < NPIX) ? x1 : x2;
    const float* p = x + (idx >> 12) * (Cc * NQ) + (idx & (NQ - 1));
    float s = 0.f, ss = 0.f;
#pragma unroll 8
    for (int k = 0; k < Cc; k++) {
        float v = p[k * NQ];
        s += v;
        ss += v * v;
    }
    float m = s * (1.0f / Cc);
    float var = ss * (1.0f / Cc) - m * m;
    float r = rsqrtf(var + EPSf);
    if (t < NPIX) { g_mean1[idx] = m; g_rstd1[idx] = r; }
    else          { g_mean2[idx] = m; g_rstd2[idx] = r; }
}

// ---------------- K2: qpos @ [W_off | W_att]  (batch-independent) ----------------
__global__ void k_qp(const float* __restrict__ W_off, const float* __restrict__ W_att,
                     const float* __restrict__ pos_scale)
{
    __shared__ float qp[Cc];
    int q = blockIdx.x;
    float ps = pos_scale[0];
    for (int k = threadIdx.x; k < Cc; k += blockDim.x) {
        int i = (k < 128) ? k : k - 128;
        // inv_freq = 10000^{-i/128}
        float invf = expf(-9.210340371976184f * (float)i * (1.0f / 128.0f));
        float ang = (float)q * invf;
        qp[k] = ((k < 128) ? sinf(ang) : cosf(ang)) * ps;
    }
    __syncthreads();
    int j = threadIdx.x;
    if (j < 48) {
        float s = 0.f;
        if (j < 32) {
            for (int k = 0; k < Cc; k++) s += qp[k] * W_off[k * 32 + j];
        } else {
            int jj = j - 32;
            for (int k = 0; k < Cc; k++) s += qp[k] * W_att[k * 16 + jj];
        }
        g_qp[q * 48 + j] = s;
    }
}

// ---------------- K3: off/att GEMM (M=128 q-tile, N=48, K=256) + softmax + loc ----------------
__global__ void __launch_bounds__(256) k_offatt(const float* __restrict__ x1,
                                                const float* __restrict__ W_off,
                                                const float* __restrict__ W_att,
                                                const float* __restrict__ ln1_g)
{
    __shared__ float As[16][128];
    __shared__ float Bs[16][48];
    __shared__ float Out[128][49];

    int b = blockIdx.y;
    int q0 = blockIdx.x * 128;
    int tid = threadIdx.x;
    int ty = tid >> 3;    // 0..31  -> 4 q rows each
    int tx = tid & 7;     // 0..7   -> 6 j cols each

    float acc[4][6];
#pragma unroll
    for (int i = 0; i < 4; i++)
#pragma unroll
        for (int j = 0; j < 6; j++) acc[i][j] = 0.f;

    const float* Ab = x1 + b * (Cc * NQ) + q0;

    for (int k0 = 0; k0 < Cc; k0 += 16) {
#pragma unroll
        for (int i = 0; i < 2; i++) {
            int lin = tid + i * 256;             // float4 id, 512 total
            int row = lin >> 5;
            int c4 = lin & 31;
            *(float4*)&As[row][c4 * 4] = *(const float4*)(Ab + (k0 + row) * NQ + c4 * 4);
        }
        if (tid < 192) {
            int row = tid / 12;
            int j0 = (tid % 12) * 4;
            int k = k0 + row;
            float gk = ln1_g[k];
            float4 v;
            if (j0 < 32) v = *(const float4*)(W_off + k * 32 + j0);
            else         v = *(const float4*)(W_att + k * 16 + (j0 - 32));
            v.x *= gk; v.y *= gk; v.z *= gk; v.w *= gk;
            *(float4*)&Bs[row][j0] = v;
        }
        __syncthreads();
#pragma unroll
        for (int kk = 0; kk < 16; kk++) {
            float a[4], bb[6];
            *(float4*)a = *(float4*)&As[kk][ty * 4];
#pragma unroll
            for (int jj = 0; jj < 6; jj++) bb[jj] = Bs[kk][tx * 6 + jj];
#pragma unroll
            for (int mi = 0; mi < 4; mi++)
#pragma unroll
                for (int jj = 0; jj < 6; jj++)
                    acc[mi][jj] += a[mi] * bb[jj];
        }
        __syncthreads();
    }
#pragma unroll
    for (int mi = 0; mi < 4; mi++)
#pragma unroll
        for (int jj = 0; jj < 6; jj++)
            Out[ty * 4 + mi][tx * 6 + jj] = acc[mi][jj];
    __syncthreads();

    if (tid < 128) {
        int qg = q0 + tid;
        int gidx = b * NQ + qg;
        float r = g_rstd1[gidx];
        float mterm = r * g_mean1[gidx];
        float vals[48];
#pragma unroll
        for (int j = 0; j < 48; j++)
            vals[j] = r * Out[tid][j] - mterm * g_gs48[j] + g_c48[j] + g_qp[qg * 48 + j];

        float* o = g_smp + (size_t)gidx * 48;
        float wpix = (float)(qg & 63);
        float hpix = (float)(qg >> 6);
#pragma unroll
        for (int h = 0; h < NHh; h++) {
#pragma unroll
            for (int p = 0; p < NPp; p++) {
                // px = w + off_x ; py = h + off_y  (exact simplification of grid_sample coords)
                o[h * 8 + p * 2]     = wpix + vals[h * 8 + p * 2];
                o[h * 8 + p * 2 + 1] = hpix + vals[h * 8 + p * 2 + 1];
            }
            float* av = &vals[32 + h * 4];
            float mx = fmaxf(fmaxf(av[0], av[1]), fmaxf(av[2], av[3]));
            float e0 = __expf(av[0] - mx), e1 = __expf(av[1] - mx);
            float e2 = __expf(av[2] - mx), e3 = __expf(av[3] - mx);
            float inv = 1.0f / (e0 + e1 + e2 + e3);
            o[32 + h * 4 + 0] = e0 * inv;
            o[32 + h * 4 + 1] = e1 * inv;
            o[32 + h * 4 + 2] = e2 * inv;
            o[32 + h * 4 + 3] = e3 * inv;
        }
    }
}

// ---------------- K4: value GEMM  value = LN2(x2) @ W_val + b_val, stored (B,Nq,C) ----------------
__global__ void __launch_bounds__(256) k_gemm_val(const float* __restrict__ x2,
                                                  const float* __restrict__ W_val,
                                                  const float* __restrict__ ln2_g)
{
    __shared__ float As[16][128];   // x2 tile: [k][q]
    __shared__ float Bs[16][128];   // g*W_val tile: [k][n]
    int b = blockIdx.z;
    int n0 = blockIdx.x * 128;
    int m0 = blockIdx.y * 128;
    int tid = threadIdx.x;
    int ty = tid >> 4, tx = tid & 15;

    float acc[8][8];
#pragma unroll
    for (int i = 0; i < 8; i++)
#pragma unroll
        for (int j = 0; j < 8; j++) acc[i][j] = 0.f;

    const float* Ab = x2 + b * (Cc * NQ) + m0;

    for (int k0 = 0; k0 < Cc; k0 += 16) {
#pragma unroll
        for (int i = 0; i < 2; i++) {
            int lin = tid + i * 256;
            int row = lin >> 5, c4 = lin & 31;
            *(float4*)&As[row][c4 * 4] = *(const float4*)(Ab + (k0 + row) * NQ + c4 * 4);
            float gk = ln2_g[k0 + row];
            float4 wv = *(const float4*)(W_val + (k0 + row) * Cc + n0 + c4 * 4);
            wv.x *= gk; wv.y *= gk; wv.z *= gk; wv.w *= gk;
            *(float4*)&Bs[row][c4 * 4] = wv;
        }
        __syncthreads();
#pragma unroll
        for (int kk = 0; kk < 16; kk++) {
            float a[8], bb[8];
            *(float4*)&a[0] = *(float4*)&As[kk][ty * 8];
            *(float4*)&a[4] = *(float4*)&As[kk][ty * 8 + 4];
            *(float4*)&bb[0] = *(float4*)&Bs[kk][tx * 8];
            *(float4*)&bb[4] = *(float4*)&Bs[kk][tx * 8 + 4];
#pragma unroll
            for (int mi = 0; mi < 8; mi++)
#pragma unroll
                for (int ni = 0; ni < 8; ni++)
                    acc[mi][ni] += a[mi] * bb[ni];
        }
        __syncthreads();
    }
#pragma unroll
    for (int mi = 0; mi < 8; mi++) {
        int qg = m0 + ty * 8 + mi;
        int gidx = b * NQ + qg;
        float r = g_rstd2[gidx];
        float mt = r * g_mean2[gidx];
        float* orow = g_value + (size_t)gidx * Cc + n0 + tx * 8;
#pragma unroll
        for (int ni = 0; ni < 8; ni++) {
            int n = n0 + tx * 8 + ni;
            orow[ni] = r * acc[mi][ni] - mt * g_vG[n] + g_vc[n];
        }
    }
}

// ---------------- K5: bilinear sampling + attention-weighted sum ----------------
__global__ void __launch_bounds__(512) k_sample()
{
    int tid = threadIdx.x;
    int warp = tid >> 5, lane = tid & 31;
    int b = blockIdx.y;
    int qg = blockIdx.x * 4 + (warp >> 2);
    int h = warp & 3;

    const float* smp = g_smp + (size_t)(b * NQ + qg) * 48;
    const float* vbase = g_value + (size_t)b * NQ * Cc + h * Dd;

    float a0 = 0.f, a1 = 0.f;
#pragma unroll
    for (int p = 0; p < 4; p++) {
        float px = smp[h * 8 + p * 2];
        float py = smp[h * 8 + p * 2 + 1];
        float aw = smp[32 + h * 4 + p];
        float fx = floorf(px), fy = floorf(py);
        int ix = (int)fx, iy = (int)fy;
        float wx = px - fx, wy = py - fy;
#pragma unroll
        for (int c = 0; c < 4; c++) {
            int cx = ix + (c & 1);
            int cy = iy + (c >> 1);
            float wgt = ((c & 1) ? wx : 1.f - wx) * ((c >> 1) ? wy : 1.f - wy) * aw;
            if (cx >= 0 && cx < Ww && cy >= 0 && cy < Hh) {
                const float* vp = vbase + (size_t)(cy * Ww + cx) * Cc;
                a0 += wgt * vp[lane];
                a1 += wgt * vp[lane + 32];
            }
        }
    }
    float* o = g_S + (size_t)(b * NQ + qg) * Cc + h * Dd;
    o[lane] = a0;
    o[lane + 32] = a1;
}

// ---------------- K6: output GEMM  out = S @ W_out + b_out + x2, written (B,C,H,W) ----------------
__global__ void __launch_bounds__(256) k_gemm_out(const float* __restrict__ W_out,
                                                  const float* __restrict__ x2,
                                                  const float* __restrict__ b_out,
                                                  float* __restrict__ out)
{
    __shared__ float As[16][128];   // W_out tile: [k=c][m=c']
    __shared__ float Bs[16][128];   // S^T tile:  [k=c][n=q]
    int b = blockIdx.z;
    int m0 = blockIdx.x * 128;      // c'
    int n0 = blockIdx.y * 128;      // q
    int tid = threadIdx.x;
    int ty = tid >> 4, tx = tid & 15;

    float acc[8][8];
#pragma unroll
    for (int i = 0; i < 8; i++)
#pragma unroll
        for (int j = 0; j < 8; j++) acc[i][j] = 0.f;

    for (int k0 = 0; k0 < Cc; k0 += 16) {
#pragma unroll
        for (int i = 0; i < 2; i++) {
            int lin = tid + i * 256;
            int row = lin >> 5, c4 = lin & 31;
            *(float4*)&As[row][c4 * 4] = *(const float4*)(W_out + (k0 + row) * Cc + m0 + c4 * 4);
        }
#pragma unroll
        for (int i = 0; i < 2; i++) {
            int lin = tid + i * 256;         // 512 float4: 128 n rows x 4 float4 of k
            int n = lin >> 2;
            int kf = lin & 3;
            float4 v = *(const float4*)(g_S + (size_t)(b * NQ + n0 + n) * Cc + k0 + kf * 4);
            Bs[kf * 4 + 0][n] = v.x;
            Bs[kf * 4 + 1][n] = v.y;
            Bs[kf * 4 + 2][n] = v.z;
            Bs[kf * 4 + 3][n] = v.w;
        }
        __syncthreads();
#pragma unroll
        for (int kk = 0; kk < 16; kk++) {
            float a[8], bb[8];
            *(float4*)&a[0] = *(float4*)&As[kk][ty * 8];
            *(float4*)&a[4] = *(float4*)&As[kk][ty * 8 + 4];
            *(float4*)&bb[0] = *(float4*)&Bs[kk][tx * 8];
            *(float4*)&bb[4] = *(float4*)&Bs[kk][tx * 8 + 4];
#pragma unroll
            for (int mi = 0; mi < 8; mi++)
#pragma unroll
                for (int ni = 0; ni < 8; ni++)
                    acc[mi][ni] += a[mi] * bb[ni];
        }
        __syncthreads();
    }
#pragma unroll
    for (int mi = 0; mi < 8; mi++) {
        int cc = m0 + ty * 8 + mi;
        float bo = b_out[cc];
        float* orow = out + ((size_t)b * Cc + cc) * NQ + n0 + tx * 8;
        const float* xrow = x2 + ((size_t)b * Cc + cc) * NQ + n0 + tx * 8;
#pragma unroll
        for (int ni = 0; ni < 8; ni++)
            orow[ni] = acc[mi][ni] + bo + xrow[ni];
    }
}

// ---------------- launch ----------------
extern "C" void kernel_launch(void* const* d_in, const int* in_sizes, int n_in,
                              void* d_out, int out_size)
{
    const float* x1        = (const float*)d_in[0];
    const float* x2        = (const float*)d_in[1];
    const float* ln1_g     = (const float*)d_in[2];
    const float* ln1_b     = (const float*)d_in[3];
    const float* ln2_g     = (const float*)d_in[4];
    const float* ln2_b     = (const float*)d_in[5];
    const float* pos_scale = (const float*)d_in[6];
    const float* W_off     = (const float*)d_in[7];
    const float* b_off     = (const float*)d_in[8];
    const float* W_att     = (const float*)d_in[9];
    const float* b_att     = (const float*)d_in[10];
    const float* W_val     = (const float*)d_in[11];
    const float* b_val     = (const float*)d_in[12];
    const float* W_out     = (const float*)d_in[13];
    const float* b_out     = (const float*)d_in[14];
    float* out = (float*)d_out;

    k_const<<<1, 256>>>(ln1_g, ln1_b, ln2_g, ln2_b, W_off, b_off, W_att, b_att, W_val, b_val);
    k_stats<<<(2 * NPIX) / 256, 256>>>(x1, x2);
    k_qp<<<NQ, 128>>>(W_off, W_att, pos_scale);
    k_offatt<<<dim3(NQ / 128, Bb), 256>>>(x1, W_off, W_att, ln1_g);
    k_gemm_val<<<dim3(Cc / 128, NQ / 128, Bb), 256>>>(x2, W_val, ln2_g);
    k_sample<<<dim3(NQ / 4, Bb), 512>>>();
    k_gemm_out<<<dim3(Cc / 128, NQ / 128, Bb), 256>>>(W_out, x2, b_out, out);
}

// round 2
// speedup vs baseline: 1.5606x; 1.5606x over previous
#include <cuda_runtime.h>
#include <math.h>
#include <stdint.h>

// Problem constants
#define Bb   8
#define Cc   256
#define Hh   64
#define Ww   64
#define NQ   4096           // H*W
#define NPIX (Bb*NQ)        // 32768
#define NHh  4
#define NPp  4
#define Dd   64
#define EPSf 1e-5f

// ---------------- scratch (static device globals; no allocation) ----------------
__device__ float g_mean1[NPIX], g_rstd1[NPIX], g_mean2[NPIX], g_rstd2[NPIX];
__device__ float g_qp[NQ * 48];        // qpos @ [W_off | W_att]
__device__ float g_c48[48];            // b + ln1_b @ W
__device__ float g_gs48[48];           // ln1_g @ W
__device__ float g_vG[Cc];             // ln2_g @ W_val
__device__ float g_vc[Cc];             // b_val + ln2_b @ W_val
__device__ float g_value[NPIX * Cc];   // (B, Nq, C): value after LN+W_val
__device__ float g_smp[NPIX * 48];     // per (b,q): 32 pixel coords + 16 softmaxed att
__device__ float g_S[NPIX * Cc];       // sampled output (B, Nq, C)

// ---------------- tf32 mma helper ----------------
__device__ __forceinline__ void mma_tf32(float* d, const uint32_t* a, const uint32_t* b)
{
    asm volatile(
        "mma.sync.aligned.m16n8k8.row.col.f32.tf32.tf32.f32 "
        "{%0,%1,%2,%3}, {%4,%5,%6,%7}, {%8,%9}, {%0,%1,%2,%3};\n"
        : "+f"(d[0]), "+f"(d[1]), "+f"(d[2]), "+f"(d[3])
        : "r"(a[0]), "r"(a[1]), "r"(a[2]), "r"(a[3]), "r"(b[0]), "r"(b[1]));
}

// ---------------- K0: tiny constant precompute ----------------
__global__ void k_const(const float* __restrict__ ln1_g, const float* __restrict__ ln1_b,
                        const float* __restrict__ ln2_g, const float* __restrict__ ln2_b,
                        const float* __restrict__ W_off, const float* __restrict__ b_off,
                        const float* __restrict__ W_att, const float* __restrict__ b_att,
                        const float* __restrict__ W_val, const float* __restrict__ b_val)
{
    int t = threadIdx.x;   // 256 threads
    float sG = 0.f, sc = 0.f;
    for (int k = 0; k < Cc; k++) {
        float w = W_val[k * Cc + t];
        sG += ln2_g[k] * w;
        sc += ln2_b[k] * w;
    }
    g_vG[t] = sG;
    g_vc[t] = sc + b_val[t];

    if (t < 48) {
        float s1 = 0.f, s2 = 0.f, bb;
        if (t < 32) {
            for (int k = 0; k < Cc; k++) {
                float w = W_off[k * 32 + t];
                s1 += ln1_b[k] * w;
                s2 += ln1_g[k] * w;
            }
            bb = b_off[t];
        } else {
            int j = t - 32;
            for (int k = 0; k < Cc; k++) {
                float w = W_att[k * 16 + j];
                s1 += ln1_b[k] * w;
                s2 += ln1_g[k] * w;
            }
            bb = b_att[j];
        }
        g_c48[t] = s1 + bb;
        g_gs48[t] = s2;
    }
}

// ---------------- K1: per-pixel mean / rstd for x1 and x2 ----------------
__global__ void k_stats(const float* __restrict__ x1, const float* __restrict__ x2)
{
    int t = blockIdx.x * blockDim.x + threadIdx.x;      // 0 .. 2*NPIX-1
    int idx = t & (NPIX - 1);
    const float* x = (t < NPIX) ? x1 : x2;
    const float* p = x + (idx >> 12) * (Cc * NQ) + (idx & (NQ - 1));
    float s = 0.f, ss = 0.f;
#pragma unroll 8
    for (int k = 0; k < Cc; k++) {
        float v = p[k * NQ];
        s += v;
        ss += v * v;
    }
    float m = s * (1.0f / Cc);
    float var = ss * (1.0f / Cc) - m * m;
    float r = rsqrtf(var + EPSf);
    if (t < NPIX) { g_mean1[idx] = m; g_rstd1[idx] = r; }
    else          { g_mean2[idx] = m; g_rstd2[idx] = r; }
}

// ---------------- K2: qpos @ [W_off | W_att]  (batch-independent) ----------------
__global__ void k_qp(const float* __restrict__ W_off, const float* __restrict__ W_att,
                     const float* __restrict__ pos_scale)
{
    __shared__ float qp[Cc];
    int q = blockIdx.x;
    float ps = pos_scale[0];
    for (int k = threadIdx.x; k < Cc; k += blockDim.x) {
        int i = (k < 128) ? k : k - 128;
        float invf = expf(-9.210340371976184f * (float)i * (1.0f / 128.0f));
        float ang = (float)q * invf;
        qp[k] = ((k < 128) ? sinf(ang) : cosf(ang)) * ps;
    }
    __syncthreads();
    int j = threadIdx.x;
    if (j < 48) {
        float s = 0.f;
        if (j < 32) {
            for (int k = 0; k < Cc; k++) s += qp[k] * W_off[k * 32 + j];
        } else {
            int jj = j - 32;
            for (int k = 0; k < Cc; k++) s += qp[k] * W_att[k * 16 + jj];
        }
        g_qp[q * 48 + j] = s;
    }
}

// ---------------- K3: off/att GEMM (M=128 q-tile, N=48, K=256) + softmax + loc ----------------
__global__ void __launch_bounds__(256) k_offatt(const float* __restrict__ x1,
                                                const float* __restrict__ W_off,
                                                const float* __restrict__ W_att,
                                                const float* __restrict__ ln1_g)
{
    __shared__ float As[16][128];
    __shared__ float Bs[16][48];
    __shared__ float Out[128][49];

    int b = blockIdx.y;
    int q0 = blockIdx.x * 128;
    int tid = threadIdx.x;
    int ty = tid >> 3;    // 0..31
    int tx = tid & 7;     // 0..7

    float acc[4][6];
#pragma unroll
    for (int i = 0; i < 4; i++)
#pragma unroll
        for (int j = 0; j < 6; j++) acc[i][j] = 0.f;

    const float* Ab = x1 + b * (Cc * NQ) + q0;

    for (int k0 = 0; k0 < Cc; k0 += 16) {
#pragma unroll
        for (int i = 0; i < 2; i++) {
            int lin = tid + i * 256;
            int row = lin >> 5;
            int c4 = lin & 31;
            *(float4*)&As[row][c4 * 4] = *(const float4*)(Ab + (k0 + row) * NQ + c4 * 4);
        }
        if (tid < 192) {
            int row = tid / 12;
            int j0 = (tid % 12) * 4;
            int k = k0 + row;
            float gk = ln1_g[k];
            float4 v;
            if (j0 < 32) v = *(const float4*)(W_off + k * 32 + j0);
            else         v = *(const float4*)(W_att + k * 16 + (j0 - 32));
            v.x *= gk; v.y *= gk; v.z *= gk; v.w *= gk;
            *(float4*)&Bs[row][j0] = v;
        }
        __syncthreads();
#pragma unroll
        for (int kk = 0; kk < 16; kk++) {
            float a[4], bb[6];
            *(float4*)a = *(float4*)&As[kk][ty * 4];
#pragma unroll
            for (int jj = 0; jj < 6; jj++) bb[jj] = Bs[kk][tx * 6 + jj];
#pragma unroll
            for (int mi = 0; mi < 4; mi++)
#pragma unroll
                for (int jj = 0; jj < 6; jj++)
                    acc[mi][jj] += a[mi] * bb[jj];
        }
        __syncthreads();
    }
#pragma unroll
    for (int mi = 0; mi < 4; mi++)
#pragma unroll
        for (int jj = 0; jj < 6; jj++)
            Out[ty * 4 + mi][tx * 6 + jj] = acc[mi][jj];
    __syncthreads();

    if (tid < 128) {
        int qg = q0 + tid;
        int gidx = b * NQ + qg;
        float r = g_rstd1[gidx];
        float mterm = r * g_mean1[gidx];
        float vals[48];
#pragma unroll
        for (int j = 0; j < 48; j++)
            vals[j] = r * Out[tid][j] - mterm * g_gs48[j] + g_c48[j] + g_qp[qg * 48 + j];

        float* o = g_smp + (size_t)gidx * 48;
        float wpix = (float)(qg & 63);
        float hpix = (float)(qg >> 6);
#pragma unroll
        for (int h = 0; h < NHh; h++) {
#pragma unroll
            for (int p = 0; p < NPp; p++) {
                o[h * 8 + p * 2]     = wpix + vals[h * 8 + p * 2];
                o[h * 8 + p * 2 + 1] = hpix + vals[h * 8 + p * 2 + 1];
            }
            float* av = &vals[32 + h * 4];
            float mx = fmaxf(fmaxf(av[0], av[1]), fmaxf(av[2], av[3]));
            float e0 = __expf(av[0] - mx), e1 = __expf(av[1] - mx);
            float e2 = __expf(av[2] - mx), e3 = __expf(av[3] - mx);
            float inv = 1.0f / (e0 + e1 + e2 + e3);
            o[32 + h * 4 + 0] = e0 * inv;
            o[32 + h * 4 + 1] = e1 * inv;
            o[32 + h * 4 + 2] = e2 * inv;
            o[32 + h * 4 + 3] = e3 * inv;
        }
    }
}

// ---------------- K4: value GEMM (tf32 tensor cores) ----------------
// value = LN2(x2) @ W_val + b_val, stored (B, Nq, C)
// A = x2 tile [k][m=q] (native layout), B = (g*W_val) tile [k][n]
__global__ void __launch_bounds__(256, 2) k_gemm_val(const float* __restrict__ x2,
                                                     const float* __restrict__ W_val,
                                                     const float* __restrict__ ln2_g)
{
    __shared__ float As[32][136];
    __shared__ float Bs[32][136];

    int b = blockIdx.z;
    int n0 = blockIdx.x * 128;
    int m0 = blockIdx.y * 128;
    int tid = threadIdx.x;
    int wid = tid >> 5, lane = tid & 31;
    int warp_m = wid & 1, warp_n = wid >> 1;
    int lr = lane >> 2, lk = lane & 3;

    float acc[4][4][4];
#pragma unroll
    for (int i = 0; i < 4; i++)
#pragma unroll
        for (int j = 0; j < 4; j++)
#pragma unroll
            for (int r = 0; r < 4; r++) acc[i][j][r] = 0.f;

    const float* Ab = x2 + b * (Cc * NQ) + m0;

    for (int k0 = 0; k0 < Cc; k0 += 32) {
#pragma unroll
        for (int i = 0; i < 4; i++) {
            int lin = tid + i * 256;          // 1024 float4
            int k = lin >> 5;
            int mf = lin & 31;
            *(float4*)&As[k][mf * 4] = *(const float4*)(Ab + (k0 + k) * NQ + mf * 4);
            float gk = ln2_g[k0 + k];
            float4 wv = *(const float4*)(W_val + (k0 + k) * Cc + n0 + mf * 4);
            wv.x *= gk; wv.y *= gk; wv.z *= gk; wv.w *= gk;
            *(float4*)&Bs[k][mf * 4] = wv;
        }
        __syncthreads();
#pragma unroll
        for (int kk = 0; kk < 4; kk++) {
            int ko = kk * 8 + lk;
            uint32_t a[4][4], bf[4][2];
#pragma unroll
            for (int mt = 0; mt < 4; mt++) {
                int r = warp_m * 64 + mt * 16 + lr;
                a[mt][0] = __float_as_uint(As[ko][r]);
                a[mt][1] = __float_as_uint(As[ko][r + 8]);
                a[mt][2] = __float_as_uint(As[ko + 4][r]);
                a[mt][3] = __float_as_uint(As[ko + 4][r + 8]);
            }
#pragma unroll
            for (int nt = 0; nt < 4; nt++) {
                int c = warp_n * 32 + nt * 8 + lr;
                bf[nt][0] = __float_as_uint(Bs[ko][c]);
                bf[nt][1] = __float_as_uint(Bs[ko + 4][c]);
            }
#pragma unroll
            for (int mt = 0; mt < 4; mt++)
#pragma unroll
                for (int nt = 0; nt < 4; nt++)
                    mma_tf32(acc[mt][nt], a[mt], bf[nt]);
        }
        __syncthreads();
    }

    // epilogue: LN-fold + bias, store (q, c) pairs
    int lc2 = (lane & 3) * 2;
#pragma unroll
    for (int mt = 0; mt < 4; mt++) {
        int q1 = m0 + warp_m * 64 + mt * 16 + lr;
        int q2 = q1 + 8;
        int g1 = b * NQ + q1, g2 = b * NQ + q2;
        float r1 = g_rstd2[g1], mm1 = r1 * g_mean2[g1];
        float r2 = g_rstd2[g2], mm2 = r2 * g_mean2[g2];
#pragma unroll
        for (int nt = 0; nt < 4; nt++) {
            int c = n0 + warp_n * 32 + nt * 8 + lc2;
            float vG0 = g_vG[c], vG1 = g_vG[c + 1];
            float vc0 = g_vc[c], vc1 = g_vc[c + 1];
            float2 o1, o2;
            o1.x = r1 * acc[mt][nt][0] - mm1 * vG0 + vc0;
            o1.y = r1 * acc[mt][nt][1] - mm1 * vG1 + vc1;
            o2.x = r2 * acc[mt][nt][2] - mm2 * vG0 + vc0;
            o2.y = r2 * acc[mt][nt][3] - mm2 * vG1 + vc1;
            *(float2*)(g_value + (size_t)g1 * Cc + c) = o1;
            *(float2*)(g_value + (size_t)g2 * Cc + c) = o2;
        }
    }
}

// ---------------- K5: bilinear sampling + attention-weighted sum ----------------
__global__ void __launch_bounds__(512) k_sample()
{
    int tid = threadIdx.x;
    int warp = tid >> 5, lane = tid & 31;
    int b = blockIdx.y;
    int qg = blockIdx.x * 4 + (warp >> 2);
    int h = warp & 3;

    const float* smp = g_smp + (size_t)(b * NQ + qg) * 48;
    const float* vbase = g_value + (size_t)b * NQ * Cc + h * Dd;

    float a0 = 0.f, a1 = 0.f;
#pragma unroll
    for (int p = 0; p < 4; p++) {
        float px = smp[h * 8 + p * 2];
        float py = smp[h * 8 + p * 2 + 1];
        float aw = smp[32 + h * 4 + p];
        float fx = floorf(px), fy = floorf(py);
        int ix = (int)fx, iy = (int)fy;
        float wx = px - fx, wy = py - fy;
#pragma unroll
        for (int c = 0; c < 4; c++) {
            int cx = ix + (c & 1);
            int cy = iy + (c >> 1);
            float wgt = ((c & 1) ? wx : 1.f - wx) * ((c >> 1) ? wy : 1.f - wy) * aw;
            if (cx >= 0 && cx < Ww && cy >= 0 && cy < Hh) {
                const float* vp = vbase + (size_t)(cy * Ww + cx) * Cc;
                a0 += wgt * vp[lane];
                a1 += wgt * vp[lane + 32];
            }
        }
    }
    float* o = g_S + (size_t)(b * NQ + qg) * Cc + h * Dd;
    o[lane] = a0;
    o[lane + 32] = a1;
}

// ---------------- K6: output GEMM (tf32 tensor cores) ----------------
// out = S @ W_out + b_out + x2, written (B, C, H, W)
// m = c' (A = W_out [k][m]), n = q (B = S^T [k][n])
__global__ void __launch_bounds__(256, 2) k_gemm_out(const float* __restrict__ W_out,
                                                     const float* __restrict__ x2,
                                                     const float* __restrict__ b_out,
                                                     float* __restrict__ out)
{
    __shared__ float As[32][136];
    __shared__ float Bs[32][136];

    int b = blockIdx.z;
    int m0 = blockIdx.x * 128;      // c'
    int n0 = blockIdx.y * 128;      // q
    int tid = threadIdx.x;
    int wid = tid >> 5, lane = tid & 31;
    int warp_m = wid & 1, warp_n = wid >> 1;
    int lr = lane >> 2, lk = lane & 3;

    float acc[4][4][4];
#pragma unroll
    for (int i = 0; i < 4; i++)
#pragma unroll
        for (int j = 0; j < 4; j++)
#pragma unroll
            for (int r = 0; r < 4; r++) acc[i][j][r] = 0.f;

    const float* Sb = g_S + (size_t)(b * NQ + n0) * Cc;

    for (int k0 = 0; k0 < Cc; k0 += 32) {
#pragma unroll
        for (int i = 0; i < 4; i++) {
            int lin = tid + i * 256;
            int k = lin >> 5;
            int mf = lin & 31;
            *(float4*)&As[k][mf * 4] = *(const float4*)(W_out + (k0 + k) * Cc + m0 + mf * 4);
        }
#pragma unroll
        for (int i = 0; i < 4; i++) {
            int lin = tid + i * 256;          // 1024 float4: 128 q x 8 kf
            int q = lin >> 3;
            int kf = lin & 7;
            float4 v = *(const float4*)(Sb + (size_t)q * Cc + k0 + kf * 4);
            Bs[kf * 4 + 0][q] = v.x;
            Bs[kf * 4 + 1][q] = v.y;
            Bs[kf * 4 + 2][q] = v.z;
            Bs[kf * 4 + 3][q] = v.w;
        }
        __syncthreads();
#pragma unroll
        for (int kk = 0; kk < 4; kk++) {
            int ko = kk * 8 + lk;
            uint32_t a[4][4], bf[4][2];
#pragma unroll
            for (int mt = 0; mt < 4; mt++) {
                int r = warp_m * 64 + mt * 16 + lr;
                a[mt][0] = __float_as_uint(As[ko][r]);
                a[mt][1] = __float_as_uint(As[ko][r + 8]);
                a[mt][2] = __float_as_uint(As[ko + 4][r]);
                a[mt][3] = __float_as_uint(As[ko + 4][r + 8]);
            }
#pragma unroll
            for (int nt = 0; nt < 4; nt++) {
                int c = warp_n * 32 + nt * 8 + lr;
                bf[nt][0] = __float_as_uint(Bs[ko][c]);
                bf[nt][1] = __float_as_uint(Bs[ko + 4][c]);
            }
#pragma unroll
            for (int mt = 0; mt < 4; mt++)
#pragma unroll
                for (int nt = 0; nt < 4; nt++)
                    mma_tf32(acc[mt][nt], a[mt], bf[nt]);
        }
        __syncthreads();
    }

    // epilogue: + b_out + x2 residual, store (c', q) pairs
    int lc2 = (lane & 3) * 2;
#pragma unroll
    for (int mt = 0; mt < 4; mt++) {
        int c1 = m0 + warp_m * 64 + mt * 16 + lr;
        int c2 = c1 + 8;
        float bo1 = b_out[c1], bo2 = b_out[c2];
        size_t base1 = ((size_t)b * Cc + c1) * NQ;
        size_t base2 = ((size_t)b * Cc + c2) * NQ;
#pragma unroll
        for (int nt = 0; nt < 4; nt++) {
            int q = n0 + warp_n * 32 + nt * 8 + lc2;
            float2 x1v = *(const float2*)(x2 + base1 + q);
            float2 x2v = *(const float2*)(x2 + base2 + q);
            float2 o1, o2;
            o1.x = acc[mt][nt][0] + bo1 + x1v.x;
            o1.y = acc[mt][nt][1] + bo1 + x1v.y;
            o2.x = acc[mt][nt][2] + bo2 + x2v.x;
            o2.y = acc[mt][nt][3] + bo2 + x2v.y;
            *(float2*)(out + base1 + q) = o1;
            *(float2*)(out + base2 + q) = o2;
        }
    }
}

// ---------------- launch ----------------
extern "C" void kernel_launch(void* const* d_in, const int* in_sizes, int n_in,
                              void* d_out, int out_size)
{
    const float* x1        = (const float*)d_in[0];
    const float* x2        = (const float*)d_in[1];
    const float* ln1_g     = (const float*)d_in[2];
    const float* ln1_b     = (const float*)d_in[3];
    const float* ln2_g     = (const float*)d_in[4];
    const float* ln2_b     = (const float*)d_in[5];
    const float* pos_scale = (const float*)d_in[6];
    const float* W_off     = (const float*)d_in[7];
    const float* b_off     = (const float*)d_in[8];
    const float* W_att     = (const float*)d_in[9];
    const float* b_att     = (const float*)d_in[10];
    const float* W_val     = (const float*)d_in[11];
    const float* b_val     = (const float*)d_in[12];
    const float* W_out     = (const float*)d_in[13];
    const float* b_out     = (const float*)d_in[14];
    float* out = (float*)d_out;

    k_const<<<1, 256>>>(ln1_g, ln1_b, ln2_g, ln2_b, W_off, b_off, W_att, b_att, W_val, b_val);
    k_stats<<<(2 * NPIX) / 256, 256>>>(x1, x2);
    k_qp<<<NQ, 128>>>(W_off, W_att, pos_scale);
    k_offatt<<<dim3(NQ / 128, Bb), 256>>>(x1, W_off, W_att, ln1_g);
    k_gemm_val<<<dim3(Cc / 128, NQ / 128, Bb), 256>>>(x2, W_val, ln2_g);
    k_sample<<<dim3(NQ / 4, Bb), 512>>>();
    k_gemm_out<<<dim3(Cc / 128, NQ / 128, Bb), 256>>>(W_out, x2, b_out, out);
}

// round 3
// speedup vs baseline: 2.3287x; 1.4922x over previous
#include <cuda_runtime.h>
#include <cuda_bf16.h>
#include <math.h>
#include <stdint.h>

// Problem constants
#define Bb   8
#define Cc   256
#define Hh   64
#define Ww   64
#define NQ   4096           // H*W
#define NPIX (Bb*NQ)        // 32768
#define NHh  4
#define NPp  4
#define Dd   64
#define EPSf 1e-5f

// ---------------- scratch (static device globals; no allocation) ----------------
__device__ float g_mean1[NPIX], g_rstd1[NPIX], g_mean2[NPIX], g_rstd2[NPIX];
__device__ float g_qp[NQ * 48];          // qpos @ [W_off | W_att]
__device__ float g_c48[48];              // b + ln1_b @ W
__device__ float g_gs48[48];             // ln1_g @ W
__device__ float g_vG[Cc];               // ln2_g @ W_val
__device__ float g_vc[Cc];               // b_val + ln2_b @ W_val
__device__ uint32_t g_value[NPIX * Cc / 2];  // bf16x2: (B,Nq,C), pair (c, c+1)
__device__ float g_smp[NPIX * 48];       // 32 pixel coords + 16 softmaxed att per (b,q)
__device__ uint32_t g_S[NPIX * Cc / 2];      // bf16x2 sampled output (B,Nq,C)

// ---------------- helpers ----------------
__device__ __forceinline__ uint32_t packbf(float lo, float hi)
{
    __nv_bfloat162 h = __floats2bfloat162_rn(lo, hi);
    return *(uint32_t*)&h;
}

__device__ __forceinline__ void mma_bf16(float* d, const uint32_t* a, const uint32_t* b)
{
    asm volatile(
        "mma.sync.aligned.m16n8k16.row.col.f32.bf16.bf16.f32 "
        "{%0,%1,%2,%3}, {%4,%5,%6,%7}, {%8,%9}, {%0,%1,%2,%3};\n"
        : "+f"(d[0]), "+f"(d[1]), "+f"(d[2]), "+f"(d[3])
        : "r"(a[0]), "r"(a[1]), "r"(a[2]), "r"(a[3]), "r"(b[0]), "r"(b[1]));
}

// ---------------- K_pre: const + stats + qpos, one launch ----------------
// grid: block 0 = const; blocks 1..256 = stats; blocks 257..4352 = qp
__global__ void __launch_bounds__(256) k_pre(
    const float* __restrict__ x1, const float* __restrict__ x2,
    const float* __restrict__ ln1_g, const float* __restrict__ ln1_b,
    const float* __restrict__ ln2_g, const float* __restrict__ ln2_b,
    const float* __restrict__ pos_scale,
    const float* __restrict__ W_off, const float* __restrict__ b_off,
    const float* __restrict__ W_att, const float* __restrict__ b_att,
    const float* __restrict__ W_val, const float* __restrict__ b_val)
{
    int bid = blockIdx.x;
    int tid = threadIdx.x;

    if (bid == 0) {
        // ---- constants ----
        float sG = 0.f, sc = 0.f;
        for (int k = 0; k < Cc; k++) {
            float w = W_val[k * Cc + tid];
            sG += ln2_g[k] * w;
            sc += ln2_b[k] * w;
        }
        g_vG[tid] = sG;
        g_vc[tid] = sc + b_val[tid];

        if (tid < 48) {
            float s1 = 0.f, s2 = 0.f, bb;
            if (tid < 32) {
                for (int k = 0; k < Cc; k++) {
                    float w = W_off[k * 32 + tid];
                    s1 += ln1_b[k] * w;
                    s2 += ln1_g[k] * w;
                }
                bb = b_off[tid];
            } else {
                int j = tid - 32;
                for (int k = 0; k < Cc; k++) {
                    float w = W_att[k * 16 + j];
                    s1 += ln1_b[k] * w;
                    s2 += ln1_g[k] * w;
                }
                bb = b_att[j];
            }
            g_c48[tid] = s1 + bb;
            g_gs48[tid] = s2;
        }
    } else if (bid <= 256) {
        // ---- per-pixel LN stats ----
        int t = (bid - 1) * 256 + tid;          // 0 .. 2*NPIX-1
        int idx = t & (NPIX - 1);
        const float* x = (t < NPIX) ? x1 : x2;
        const float* p = x + (idx >> 12) * (Cc * NQ) + (idx & (NQ - 1));
        float s = 0.f, ss = 0.f;
#pragma unroll 8
        for (int k = 0; k < Cc; k++) {
            float v = p[k * NQ];
            s += v;
            ss += v * v;
        }
        float m = s * (1.0f / Cc);
        float var = ss * (1.0f / Cc) - m * m;
        float r = rsqrtf(var + EPSf);
        if (t < NPIX) { g_mean1[idx] = m; g_rstd1[idx] = r; }
        else          { g_mean2[idx] = m; g_rstd2[idx] = r; }
    } else {
        // ---- qpos projection ----
        __shared__ float qp[Cc];
        int q = bid - 257;
        float ps = pos_scale[0];
        {
            int k = tid;
            int i = (k < 128) ? k : k - 128;
            float invf = expf(-9.210340371976184f * (float)i * (1.0f / 128.0f));
            float ang = (float)q * invf;
            qp[k] = ((k < 128) ? sinf(ang) : cosf(ang)) * ps;
        }
        __syncthreads();
        if (tid < 192) {
            int j = tid >> 2;
            int part = tid & 3;
            float s = 0.f;
            int kk0 = part * 64;
            if (j < 32) {
                for (int k = kk0; k < kk0 + 64; k++) s += qp[k] * W_off[k * 32 + j];
            } else {
                int jj = j - 32;
                for (int k = kk0; k < kk0 + 64; k++) s += qp[k] * W_att[k * 16 + jj];
            }
            s += __shfl_xor_sync(0xFFFFFFFFu, s, 1);
            s += __shfl_xor_sync(0xFFFFFFFFu, s, 2);
            if (part == 0) g_qp[q * 48 + j] = s;
        }
    }
}

// ---------------- K3: off/att GEMM (bf16 mma) + softmax + loc ----------------
// M=128 q-tile, N=64 (48 used), K=256
__global__ void __launch_bounds__(256, 2) k_offatt(const float* __restrict__ x1,
                                                   const float* __restrict__ W_off,
                                                   const float* __restrict__ W_att,
                                                   const float* __restrict__ ln1_g)
{
    __shared__ uint32_t As2[16][136];   // bf16x2 (k,k+1) x m
    __shared__ uint32_t Bs2[16][72];    // bf16x2 (k,k+1) x j (64 cols)
    __shared__ float Out[128][52];

    int b = blockIdx.y;
    int q0 = blockIdx.x * 128;
    int tid = threadIdx.x;
    int wid = tid >> 5, lane = tid & 31;
    int warp_m = wid & 1, warp_n = wid >> 1;   // warp_n 0..3, 16 cols each
    int lr = lane >> 2, lk = lane & 3;

    float acc[4][2][4];
#pragma unroll
    for (int i = 0; i < 4; i++)
#pragma unroll
        for (int j = 0; j < 2; j++)
#pragma unroll
            for (int r = 0; r < 4; r++) acc[i][j][r] = 0.f;

    const float* Ab = x1 + b * (Cc * NQ) + q0;

    for (int k0 = 0; k0 < Cc; k0 += 32) {
        // A: pack 32 k-rows x 128 m into bf16x2
#pragma unroll
        for (int i = 0; i < 2; i++) {
            int lin = tid + i * 256;            // 512
            int k2 = lin >> 5, mf = lin & 31;
            float4 alo = *(const float4*)(Ab + (k0 + 2 * k2) * NQ + mf * 4);
            float4 ahi = *(const float4*)(Ab + (k0 + 2 * k2 + 1) * NQ + mf * 4);
            uint4 u;
            u.x = packbf(alo.x, ahi.x); u.y = packbf(alo.y, ahi.y);
            u.z = packbf(alo.z, ahi.z); u.w = packbf(alo.w, ahi.w);
            *(uint4*)&As2[k2][mf * 4] = u;
        }
        // B: 16 k2 x 64 cols (W_off | W_att | zeros), scaled by ln1_g
#pragma unroll
        for (int i = 0; i < 4; i++) {
            int lin = tid + i * 256;            // 1024
            int j = lin & 63;
            int k2 = lin >> 6;
            int k = k0 + 2 * k2;
            float lo = 0.f, hi = 0.f;
            if (j < 32) {
                lo = W_off[k * 32 + j] * ln1_g[k];
                hi = W_off[(k + 1) * 32 + j] * ln1_g[k + 1];
            } else if (j < 48) {
                int jj = j - 32;
                lo = W_att[k * 16 + jj] * ln1_g[k];
                hi = W_att[(k + 1) * 16 + jj] * ln1_g[k + 1];
            }
            Bs2[k2][j] = packbf(lo, hi);
        }
        __syncthreads();
#pragma unroll
        for (int kk = 0; kk < 2; kk++) {
            int base = kk * 8;
            uint32_t a[4][4], bf[2][2];
#pragma unroll
            for (int mt = 0; mt < 4; mt++) {
                int r = warp_m * 64 + mt * 16 + lr;
                a[mt][0] = As2[base + lk][r];
                a[mt][1] = As2[base + lk][r + 8];
                a[mt][2] = As2[base + lk + 4][r];
                a[mt][3] = As2[base + lk + 4][r + 8];
            }
#pragma unroll
            for (int nt = 0; nt < 2; nt++) {
                int c = warp_n * 16 + nt * 8 + lr;
                bf[nt][0] = Bs2[base + lk][c];
                bf[nt][1] = Bs2[base + lk + 4][c];
            }
#pragma unroll
            for (int mt = 0; mt < 4; mt++)
#pragma unroll
                for (int nt = 0; nt < 2; nt++)
                    mma_bf16(acc[mt][nt], a[mt], bf[nt]);
        }
        __syncthreads();
    }

    // scatter acc to Out (only cols < 48)
    int lc2 = (lane & 3) * 2;
#pragma unroll
    for (int mt = 0; mt < 4; mt++) {
#pragma unroll
        for (int nt = 0; nt < 2; nt++) {
            int c = warp_n * 16 + nt * 8 + lc2;
            if (c < 48) {
                int r = warp_m * 64 + mt * 16 + lr;
                *(float2*)&Out[r][c]     = make_float2(acc[mt][nt][0], acc[mt][nt][1]);
                *(float2*)&Out[r + 8][c] = make_float2(acc[mt][nt][2], acc[mt][nt][3]);
            }
        }
    }
    __syncthreads();

    if (tid < 128) {
        int qg = q0 + tid;
        int gidx = b * NQ + qg;
        float r = g_rstd1[gidx];
        float mterm = r * g_mean1[gidx];
        float vals[48];
#pragma unroll
        for (int j = 0; j < 48; j++)
            vals[j] = r * Out[tid][j] - mterm * g_gs48[j] + g_c48[j] + g_qp[qg * 48 + j];

        float* o = g_smp + (size_t)gidx * 48;
        float wpix = (float)(qg & 63);
        float hpix = (float)(qg >> 6);
#pragma unroll
        for (int h = 0; h < NHh; h++) {
#pragma unroll
            for (int p = 0; p < NPp; p++) {
                o[h * 8 + p * 2]     = wpix + vals[h * 8 + p * 2];
                o[h * 8 + p * 2 + 1] = hpix + vals[h * 8 + p * 2 + 1];
            }
            float* av = &vals[32 + h * 4];
            float mx = fmaxf(fmaxf(av[0], av[1]), fmaxf(av[2], av[3]));
            float e0 = __expf(av[0] - mx), e1 = __expf(av[1] - mx);
            float e2 = __expf(av[2] - mx), e3 = __expf(av[3] - mx);
            float inv = 1.0f / (e0 + e1 + e2 + e3);
            o[32 + h * 4 + 0] = e0 * inv;
            o[32 + h * 4 + 1] = e1 * inv;
            o[32 + h * 4 + 2] = e2 * inv;
            o[32 + h * 4 + 3] = e3 * inv;
        }
    }
}

// ---------------- K4: value GEMM (bf16 mma) -> g_value bf16 ----------------
__global__ void __launch_bounds__(256, 2) k_gemm_val(const float* __restrict__ x2,
                                                     const float* __restrict__ W_val,
                                                     const float* __restrict__ ln2_g)
{
    __shared__ uint32_t As2[16][136];
    __shared__ uint32_t Bs2[16][136];

    int b = blockIdx.z;
    int n0 = blockIdx.x * 128;
    int m0 = blockIdx.y * 128;
    int tid = threadIdx.x;
    int wid = tid >> 5, lane = tid & 31;
    int warp_m = wid & 1, warp_n = wid >> 1;
    int lr = lane >> 2, lk = lane & 3;

    float acc[4][4][4];
#pragma unroll
    for (int i = 0; i < 4; i++)
#pragma unroll
        for (int j = 0; j < 4; j++)
#pragma unroll
            for (int r = 0; r < 4; r++) acc[i][j][r] = 0.f;

    const float* Ab = x2 + b * (Cc * NQ) + m0;

    for (int k0 = 0; k0 < Cc; k0 += 32) {
#pragma unroll
        for (int i = 0; i < 2; i++) {
            int lin = tid + i * 256;
            int k2 = lin >> 5, mf = lin & 31;
            int k = k0 + 2 * k2;
            float4 alo = *(const float4*)(Ab + k * NQ + mf * 4);
            float4 ahi = *(const float4*)(Ab + (k + 1) * NQ + mf * 4);
            uint4 ua;
            ua.x = packbf(alo.x, ahi.x); ua.y = packbf(alo.y, ahi.y);
            ua.z = packbf(alo.z, ahi.z); ua.w = packbf(alo.w, ahi.w);
            *(uint4*)&As2[k2][mf * 4] = ua;
            float g0 = ln2_g[k], g1 = ln2_g[k + 1];
            float4 blo = *(const float4*)(W_val + k * Cc + n0 + mf * 4);
            float4 bhi = *(const float4*)(W_val + (k + 1) * Cc + n0 + mf * 4);
            uint4 ub;
            ub.x = packbf(blo.x * g0, bhi.x * g1); ub.y = packbf(blo.y * g0, bhi.y * g1);
            ub.z = packbf(blo.z * g0, bhi.z * g1); ub.w = packbf(blo.w * g0, bhi.w * g1);
            *(uint4*)&Bs2[k2][mf * 4] = ub;
        }
        __syncthreads();
#pragma unroll
        for (int kk = 0; kk < 2; kk++) {
            int base = kk * 8;
            uint32_t a[4][4], bf[4][2];
#pragma unroll
            for (int mt = 0; mt < 4; mt++) {
                int r = warp_m * 64 + mt * 16 + lr;
                a[mt][0] = As2[base + lk][r];
                a[mt][1] = As2[base + lk][r + 8];
                a[mt][2] = As2[base + lk + 4][r];
                a[mt][3] = As2[base + lk + 4][r + 8];
            }
#pragma unroll
            for (int nt = 0; nt < 4; nt++) {
                int c = warp_n * 32 + nt * 8 + lr;
                bf[nt][0] = Bs2[base + lk][c];
                bf[nt][1] = Bs2[base + lk + 4][c];
            }
#pragma unroll
            for (int mt = 0; mt < 4; mt++)
#pragma unroll
                for (int nt = 0; nt < 4; nt++)
                    mma_bf16(acc[mt][nt], a[mt], bf[nt]);
        }
        __syncthreads();
    }

    // epilogue: LN-fold + bias -> bf16x2 store
    int lc2 = (lane & 3) * 2;
#pragma unroll
    for (int mt = 0; mt < 4; mt++) {
        int q1 = m0 + warp_m * 64 + mt * 16 + lr;
        int q2 = q1 + 8;
        int g1 = b * NQ + q1, g2 = b * NQ + q2;
        float r1 = g_rstd2[g1], mm1 = r1 * g_mean2[g1];
        float r2 = g_rstd2[g2], mm2 = r2 * g_mean2[g2];
#pragma unroll
        for (int nt = 0; nt < 4; nt++) {
            int c = n0 + warp_n * 32 + nt * 8 + lc2;
            float vG0 = g_vG[c], vG1 = g_vG[c + 1];
            float vc0 = g_vc[c], vc1 = g_vc[c + 1];
            g_value[(size_t)g1 * 128 + (c >> 1)] =
                packbf(r1 * acc[mt][nt][0] - mm1 * vG0 + vc0,
                       r1 * acc[mt][nt][1] - mm1 * vG1 + vc1);
            g_value[(size_t)g2 * 128 + (c >> 1)] =
                packbf(r2 * acc[mt][nt][2] - mm2 * vG0 + vc0,
                       r2 * acc[mt][nt][3] - mm2 * vG1 + vc1);
        }
    }
}

// ---------------- K5: bilinear sampling (bf16 value -> bf16 S) ----------------
__global__ void __launch_bounds__(512) k_sample()
{
    int tid = threadIdx.x;
    int warp = tid >> 5, lane = tid & 31;
    int b = blockIdx.y;
    int qg = blockIdx.x * 4 + (warp >> 2);
    int h = warp & 3;

    const float* smp = g_smp + (size_t)(b * NQ + qg) * 48;
    const uint32_t* vbase = g_value + (size_t)b * NQ * 128 + h * 32 + lane;

    float a0 = 0.f, a1 = 0.f;
#pragma unroll
    for (int p = 0; p < 4; p++) {
        float px = smp[h * 8 + p * 2];
        float py = smp[h * 8 + p * 2 + 1];
        float aw = smp[32 + h * 4 + p];
        float fx = floorf(px), fy = floorf(py);
        int ix = (int)fx, iy = (int)fy;
        float wx = px - fx, wy = py - fy;
#pragma unroll
        for (int c = 0; c < 4; c++) {
            int cx = ix + (c & 1);
            int cy = iy + (c >> 1);
            float wgt = ((c & 1) ? wx : 1.f - wx) * ((c >> 1) ? wy : 1.f - wy) * aw;
            if (cx >= 0 && cx < Ww && cy >= 0 && cy < Hh) {
                uint32_t v = vbase[(size_t)(cy * Ww + cx) * 128];
                __nv_bfloat162 bv = *(__nv_bfloat162*)&v;
                a0 += wgt * __bfloat162float(bv.x);
                a1 += wgt * __bfloat162float(bv.y);
            }
        }
    }
    g_S[(size_t)(b * NQ + qg) * 128 + h * 32 + lane] = packbf(a0, a1);
}

// ---------------- K6: output GEMM (bf16 mma) ----------------
// out = S @ W_out + b_out + x2, written (B, C, H, W);  m = c', n = q
__global__ void __launch_bounds__(256, 2) k_gemm_out(const float* __restrict__ W_out,
                                                     const float* __restrict__ x2,
                                                     const float* __restrict__ b_out,
                                                     float* __restrict__ out)
{
    __shared__ uint32_t As2[16][136];
    __shared__ uint32_t Bs2[16][136];

    int b = blockIdx.z;
    int m0 = blockIdx.x * 128;      // c'
    int n0 = blockIdx.y * 128;      // q
    int tid = threadIdx.x;
    int wid = tid >> 5, lane = tid & 31;
    int warp_m = wid & 1, warp_n = wid >> 1;
    int lr = lane >> 2, lk = lane & 3;

    float acc[4][4][4];
#pragma unroll
    for (int i = 0; i < 4; i++)
#pragma unroll
        for (int j = 0; j < 4; j++)
#pragma unroll
            for (int r = 0; r < 4; r++) acc[i][j][r] = 0.f;

    const uint32_t* Sb = g_S + (size_t)(b * NQ + n0) * 128;

    for (int k0 = 0; k0 < Cc; k0 += 32) {
        // A: W_out pack
#pragma unroll
        for (int i = 0; i < 2; i++) {
            int lin = tid + i * 256;
            int k2 = lin >> 5, mf = lin & 31;
            int k = k0 + 2 * k2;
            float4 alo = *(const float4*)(W_out + k * Cc + m0 + mf * 4);
            float4 ahi = *(const float4*)(W_out + (k + 1) * Cc + m0 + mf * 4);
            uint4 u;
            u.x = packbf(alo.x, ahi.x); u.y = packbf(alo.y, ahi.y);
            u.z = packbf(alo.z, ahi.z); u.w = packbf(alo.w, ahi.w);
            *(uint4*)&As2[k2][mf * 4] = u;
        }
        // B: S is already bf16x2 (q, k-pair) — direct copy to [k2][q]
#pragma unroll
        for (int i = 0; i < 8; i++) {
            int lin = tid + i * 256;            // 2048
            int k2 = lin & 15, q = lin >> 4;
            Bs2[k2][q] = Sb[(size_t)q * 128 + (k0 >> 1) + k2];
        }
        __syncthreads();
#pragma unroll
        for (int kk = 0; kk < 2; kk++) {
            int base = kk * 8;
            uint32_t a[4][4], bf[4][2];
#pragma unroll
            for (int mt = 0; mt < 4; mt++) {
                int r = warp_m * 64 + mt * 16 + lr;
                a[mt][0] = As2[base + lk][r];
                a[mt][1] = As2[base + lk][r + 8];
                a[mt][2] = As2[base + lk + 4][r];
                a[mt][3] = As2[base + lk + 4][r + 8];
            }
#pragma unroll
            for (int nt = 0; nt < 4; nt++) {
                int c = warp_n * 32 + nt * 8 + lr;
                bf[nt][0] = Bs2[base + lk][c];
                bf[nt][1] = Bs2[base + lk + 4][c];
            }
#pragma unroll
            for (int mt = 0; mt < 4; mt++)
#pragma unroll
                for (int nt = 0; nt < 4; nt++)
                    mma_bf16(acc[mt][nt], a[mt], bf[nt]);
        }
        __syncthreads();
    }

    // epilogue: + b_out + x2 residual (fp32 out)
    int lc2 = (lane & 3) * 2;
#pragma unroll
    for (int mt = 0; mt < 4; mt++) {
        int c1 = m0 + warp_m * 64 + mt * 16 + lr;
        int c2 = c1 + 8;
        float bo1 = b_out[c1], bo2 = b_out[c2];
        size_t base1 = ((size_t)b * Cc + c1) * NQ;
        size_t base2 = ((size_t)b * Cc + c2) * NQ;
#pragma unroll
        for (int nt = 0; nt < 4; nt++) {
            int q = n0 + warp_n * 32 + nt * 8 + lc2;
            float2 x1v = *(const float2*)(x2 + base1 + q);
            float2 x2v = *(const float2*)(x2 + base2 + q);
            float2 o1, o2;
            o1.x = acc[mt][nt][0] + bo1 + x1v.x;
            o1.y = acc[mt][nt][1] + bo1 + x1v.y;
            o2.x = acc[mt][nt][2] + bo2 + x2v.x;
            o2.y = acc[mt][nt][3] + bo2 + x2v.y;
            *(float2*)(out + base1 + q) = o1;
            *(float2*)(out + base2 + q) = o2;
        }
    }
}

// ---------------- launch ----------------
extern "C" void kernel_launch(void* const* d_in, const int* in_sizes, int n_in,
                              void* d_out, int out_size)
{
    const float* x1        = (const float*)d_in[0];
    const float* x2        = (const float*)d_in[1];
    const float* ln1_g     = (const float*)d_in[2];
    const float* ln1_b     = (const float*)d_in[3];
    const float* ln2_g     = (const float*)d_in[4];
    const float* ln2_b     = (const float*)d_in[5];
    const float* pos_scale = (const float*)d_in[6];
    const float* W_off     = (const float*)d_in[7];
    const float* b_off     = (const float*)d_in[8];
    const float* W_att     = (const float*)d_in[9];
    const float* b_att     = (const float*)d_in[10];
    const float* W_val     = (const float*)d_in[11];
    const float* b_val     = (const float*)d_in[12];
    const float* W_out     = (const float*)d_in[13];
    const float* b_out     = (const float*)d_in[14];
    float* out = (float*)d_out;

    k_pre<<<257 + NQ, 256>>>(x1, x2, ln1_g, ln1_b, ln2_g, ln2_b, pos_scale,
                             W_off, b_off, W_att, b_att, W_val, b_val);
    k_offatt<<<dim3(NQ / 128, Bb), 256>>>(x1, W_off, W_att, ln1_g);
    k_gemm_val<<<dim3(Cc / 128, NQ / 128, Bb), 256>>>(x2, W_val, ln2_g);
    k_sample<<<dim3(NQ / 4, Bb), 512>>>();
    k_gemm_out<<<dim3(Cc / 128, NQ / 128, Bb), 256>>>(W_out, x2, b_out, out);
}

// round 4
// speedup vs baseline: 2.5482x; 1.0942x over previous
#include <cuda_runtime.h>
#include <cuda_bf16.h>
#include <math.h>
#include <stdint.h>

// Problem constants
#define Bb   8
#define Cc   256
#define Hh   64
#define Ww   64
#define NQ   4096           // H*W
#define NPIX (Bb*NQ)        // 32768
#define NHh  4
#define NPp  4
#define Dd   64
#define EPSf 1e-5f

// ---------------- scratch (static device globals; no allocation) ----------------
__device__ float g_mean1[NPIX], g_rstd1[NPIX], g_mean2[NPIX], g_rstd2[NPIX];
__device__ float g_qp[NQ * 48];          // qpos @ [W_off | W_att]
__device__ float g_c48[48];              // b + ln1_b @ W
__device__ float g_gs48[48];             // ln1_g @ W
__device__ float g_vG[Cc];               // ln2_g @ W_val
__device__ float g_vc[Cc];               // b_val + ln2_b @ W_val
__device__ uint32_t g_value[NPIX * Cc / 2];  // bf16x2: (B,Nq,C), pair (c, c+1)
__device__ uint2 g_pairs[(size_t)NPIX * 64]; // per (b,q,h): 16 x (pixel offset, weight)
__device__ uint32_t g_S[NPIX * Cc / 2];      // bf16x2 sampled output (B,Nq,C)

// ---------------- helpers ----------------
__device__ __forceinline__ uint32_t packbf(float lo, float hi)
{
    __nv_bfloat162 h = __floats2bfloat162_rn(lo, hi);
    return *(uint32_t*)&h;
}

__device__ __forceinline__ void mma_bf16(float* d, const uint32_t* a, const uint32_t* b)
{
    asm volatile(
        "mma.sync.aligned.m16n8k16.row.col.f32.bf16.bf16.f32 "
        "{%0,%1,%2,%3}, {%4,%5,%6,%7}, {%8,%9}, {%0,%1,%2,%3};\n"
        : "+f"(d[0]), "+f"(d[1]), "+f"(d[2]), "+f"(d[3])
        : "r"(a[0]), "r"(a[1]), "r"(a[2]), "r"(a[3]), "r"(b[0]), "r"(b[1]));
}

// ---------------- K_pre: const + stats + qpos, one launch ----------------
__global__ void __launch_bounds__(256) k_pre(
    const float* __restrict__ x1, const float* __restrict__ x2,
    const float* __restrict__ ln1_g, const float* __restrict__ ln1_b,
    const float* __restrict__ ln2_g, const float* __restrict__ ln2_b,
    const float* __restrict__ pos_scale,
    const float* __restrict__ W_off, const float* __restrict__ b_off,
    const float* __restrict__ W_att, const float* __restrict__ b_att,
    const float* __restrict__ W_val, const float* __restrict__ b_val)
{
    int bid = blockIdx.x;
    int tid = threadIdx.x;

    if (bid == 0) {
        float sG = 0.f, sc = 0.f;
        for (int k = 0; k < Cc; k++) {
            float w = W_val[k * Cc + tid];
            sG += ln2_g[k] * w;
            sc += ln2_b[k] * w;
        }
        g_vG[tid] = sG;
        g_vc[tid] = sc + b_val[tid];

        if (tid < 48) {
            float s1 = 0.f, s2 = 0.f, bb;
            if (tid < 32) {
                for (int k = 0; k < Cc; k++) {
                    float w = W_off[k * 32 + tid];
                    s1 += ln1_b[k] * w;
                    s2 += ln1_g[k] * w;
                }
                bb = b_off[tid];
            } else {
                int j = tid - 32;
                for (int k = 0; k < Cc; k++) {
                    float w = W_att[k * 16 + j];
                    s1 += ln1_b[k] * w;
                    s2 += ln1_g[k] * w;
                }
                bb = b_att[j];
            }
            g_c48[tid] = s1 + bb;
            g_gs48[tid] = s2;
        }
    } else if (bid <= 256) {
        int t = (bid - 1) * 256 + tid;          // 0 .. 2*NPIX-1
        int idx = t & (NPIX - 1);
        const float* x = (t < NPIX) ? x1 : x2;
        const float* p = x + (idx >> 12) * (Cc * NQ) + (idx & (NQ - 1));
        float s = 0.f, ss = 0.f;
#pragma unroll 8
        for (int k = 0; k < Cc; k++) {
            float v = p[k * NQ];
            s += v;
            ss += v * v;
        }
        float m = s * (1.0f / Cc);
        float var = ss * (1.0f / Cc) - m * m;
        float r = rsqrtf(var + EPSf);
        if (t < NPIX) { g_mean1[idx] = m; g_rstd1[idx] = r; }
        else          { g_mean2[idx] = m; g_rstd2[idx] = r; }
    } else {
        __shared__ float qp[Cc];
        int q = bid - 257;
        float ps = pos_scale[0];
        {
            int k = tid;
            int i = (k < 128) ? k : k - 128;
            float invf = expf(-9.210340371976184f * (float)i * (1.0f / 128.0f));
            float ang = (float)q * invf;
            qp[k] = ((k < 128) ? sinf(ang) : cosf(ang)) * ps;
        }
        __syncthreads();
        if (tid < 192) {
            int j = tid >> 2;
            int part = tid & 3;
            float s = 0.f;
            int kk0 = part * 64;
            if (j < 32) {
                for (int k = kk0; k < kk0 + 64; k++) s += qp[k] * W_off[k * 32 + j];
            } else {
                int jj = j - 32;
                for (int k = kk0; k < kk0 + 64; k++) s += qp[k] * W_att[k * 16 + jj];
            }
            s += __shfl_xor_sync(0xFFFFFFFFu, s, 1);
            s += __shfl_xor_sync(0xFFFFFFFFu, s, 2);
            if (part == 0) g_qp[q * 48 + j] = s;
        }
    }
}

// ---------------- K3: off/att GEMM (bf16 mma) + softmax + sampler-operand precompute ----------------
__global__ void __launch_bounds__(256, 2) k_offatt(const float* __restrict__ x1,
                                                   const float* __restrict__ W_off,
                                                   const float* __restrict__ W_att,
                                                   const float* __restrict__ ln1_g)
{
    __shared__ uint32_t As2[16][136];
    __shared__ uint32_t Bs2[16][72];
    __shared__ float Out[128][52];

    int b = blockIdx.y;
    int q0 = blockIdx.x * 128;
    int tid = threadIdx.x;
    int wid = tid >> 5, lane = tid & 31;
    int warp_m = wid & 1, warp_n = wid >> 1;
    int lr = lane >> 2, lk = lane & 3;

    float acc[4][2][4];
#pragma unroll
    for (int i = 0; i < 4; i++)
#pragma unroll
        for (int j = 0; j < 2; j++)
#pragma unroll
            for (int r = 0; r < 4; r++) acc[i][j][r] = 0.f;

    const float* Ab = x1 + b * (Cc * NQ) + q0;

    for (int k0 = 0; k0 < Cc; k0 += 32) {
#pragma unroll
        for (int i = 0; i < 2; i++) {
            int lin = tid + i * 256;
            int k2 = lin >> 5, mf = lin & 31;
            float4 alo = *(const float4*)(Ab + (k0 + 2 * k2) * NQ + mf * 4);
            float4 ahi = *(const float4*)(Ab + (k0 + 2 * k2 + 1) * NQ + mf * 4);
            uint4 u;
            u.x = packbf(alo.x, ahi.x); u.y = packbf(alo.y, ahi.y);
            u.z = packbf(alo.z, ahi.z); u.w = packbf(alo.w, ahi.w);
            *(uint4*)&As2[k2][mf * 4] = u;
        }
#pragma unroll
        for (int i = 0; i < 4; i++) {
            int lin = tid + i * 256;
            int j = lin & 63;
            int k2 = lin >> 6;
            int k = k0 + 2 * k2;
            float lo = 0.f, hi = 0.f;
            if (j < 32) {
                lo = W_off[k * 32 + j] * ln1_g[k];
                hi = W_off[(k + 1) * 32 + j] * ln1_g[k + 1];
            } else if (j < 48) {
                int jj = j - 32;
                lo = W_att[k * 16 + jj] * ln1_g[k];
                hi = W_att[(k + 1) * 16 + jj] * ln1_g[k + 1];
            }
            Bs2[k2][j] = packbf(lo, hi);
        }
        __syncthreads();
#pragma unroll
        for (int kk = 0; kk < 2; kk++) {
            int base = kk * 8;
            uint32_t a[4][4], bf[2][2];
#pragma unroll
            for (int mt = 0; mt < 4; mt++) {
                int r = warp_m * 64 + mt * 16 + lr;
                a[mt][0] = As2[base + lk][r];
                a[mt][1] = As2[base + lk][r + 8];
                a[mt][2] = As2[base + lk + 4][r];
                a[mt][3] = As2[base + lk + 4][r + 8];
            }
#pragma unroll
            for (int nt = 0; nt < 2; nt++) {
                int c = warp_n * 16 + nt * 8 + lr;
                bf[nt][0] = Bs2[base + lk][c];
                bf[nt][1] = Bs2[base + lk + 4][c];
            }
#pragma unroll
            for (int mt = 0; mt < 4; mt++)
#pragma unroll
                for (int nt = 0; nt < 2; nt++)
                    mma_bf16(acc[mt][nt], a[mt], bf[nt]);
        }
        __syncthreads();
    }

    int lc2 = (lane & 3) * 2;
#pragma unroll
    for (int mt = 0; mt < 4; mt++) {
#pragma unroll
        for (int nt = 0; nt < 2; nt++) {
            int c = warp_n * 16 + nt * 8 + lc2;
            if (c < 48) {
                int r = warp_m * 64 + mt * 16 + lr;
                *(float2*)&Out[r][c]     = make_float2(acc[mt][nt][0], acc[mt][nt][1]);
                *(float2*)&Out[r + 8][c] = make_float2(acc[mt][nt][2], acc[mt][nt][3]);
            }
        }
    }
    __syncthreads();

    if (tid < 128) {
        int qg = q0 + tid;
        int gidx = b * NQ + qg;
        float r = g_rstd1[gidx];
        float mterm = r * g_mean1[gidx];
        float vals[48];
#pragma unroll
        for (int j = 0; j < 48; j++)
            vals[j] = r * Out[tid][j] - mterm * g_gs48[j] + g_c48[j] + g_qp[qg * 48 + j];

        float wpix = (float)(qg & 63);
        float hpix = (float)(qg >> 6);
#pragma unroll
        for (int h = 0; h < NHh; h++) {
            // softmax over the 4 points
            float* av = &vals[32 + h * 4];
            float mx = fmaxf(fmaxf(av[0], av[1]), fmaxf(av[2], av[3]));
            float e0 = __expf(av[0] - mx), e1 = __expf(av[1] - mx);
            float e2 = __expf(av[2] - mx), e3 = __expf(av[3] - mx);
            float inv = 1.0f / (e0 + e1 + e2 + e3);
            float aw[4] = {e0 * inv, e1 * inv, e2 * inv, e3 * inv};

            uint2* pp = g_pairs + ((size_t)gidx * 4 + h) * 16;
#pragma unroll
            for (int p = 0; p < NPp; p++) {
                float px = wpix + vals[h * 8 + p * 2];
                float py = hpix + vals[h * 8 + p * 2 + 1];
                float fx = floorf(px), fy = floorf(py);
                int ix = (int)fx, iy = (int)fy;
                float wx = px - fx, wy = py - fy;
                float a = aw[p];
                uint4 st0, st1;
#pragma unroll
                for (int c = 0; c < 4; c++) {
                    int cx = ix + (c & 1);
                    int cy = iy + (c >> 1);
                    bool valid = (cx >= 0) & (cx < Ww) & (cy >= 0) & (cy < Hh);
                    float wgt = valid ? ((c & 1) ? wx : 1.f - wx) * ((c >> 1) ? wy : 1.f - wy) * a : 0.f;
                    uint32_t off = valid ? (uint32_t)(cy * Ww + cx) : 0u;
                    if (c == 0) { st0.x = off; st0.y = __float_as_uint(wgt); }
                    if (c == 1) { st0.z = off; st0.w = __float_as_uint(wgt); }
                    if (c == 2) { st1.x = off; st1.y = __float_as_uint(wgt); }
                    if (c == 3) { st1.z = off; st1.w = __float_as_uint(wgt); }
                }
                *(uint4*)&pp[p * 4]     = st0;
                *(uint4*)&pp[p * 4 + 2] = st1;
            }
        }
    }
}

// ---------------- K4: value GEMM (bf16 mma) -> g_value bf16 ----------------
__global__ void __launch_bounds__(256, 2) k_gemm_val(const float* __restrict__ x2,
                                                     const float* __restrict__ W_val,
                                                     const float* __restrict__ ln2_g)
{
    __shared__ uint32_t As2[16][136];
    __shared__ uint32_t Bs2[16][136];

    int b = blockIdx.z;
    int n0 = blockIdx.x * 128;
    int m0 = blockIdx.y * 128;
    int tid = threadIdx.x;
    int wid = tid >> 5, lane = tid & 31;
    int warp_m = wid & 1, warp_n = wid >> 1;
    int lr = lane >> 2, lk = lane & 3;

    float acc[4][4][4];
#pragma unroll
    for (int i = 0; i < 4; i++)
#pragma unroll
        for (int j = 0; j < 4; j++)
#pragma unroll
            for (int r = 0; r < 4; r++) acc[i][j][r] = 0.f;

    const float* Ab = x2 + b * (Cc * NQ) + m0;

    for (int k0 = 0; k0 < Cc; k0 += 32) {
#pragma unroll
        for (int i = 0; i < 2; i++) {
            int lin = tid + i * 256;
            int k2 = lin >> 5, mf = lin & 31;
            int k = k0 + 2 * k2;
            float4 alo = *(const float4*)(Ab + k * NQ + mf * 4);
            float4 ahi = *(const float4*)(Ab + (k + 1) * NQ + mf * 4);
            uint4 ua;
            ua.x = packbf(alo.x, ahi.x); ua.y = packbf(alo.y, ahi.y);
            ua.z = packbf(alo.z, ahi.z); ua.w = packbf(alo.w, ahi.w);
            *(uint4*)&As2[k2][mf * 4] = ua;
            float g0 = ln2_g[k], g1 = ln2_g[k + 1];
            float4 blo = *(const float4*)(W_val + k * Cc + n0 + mf * 4);
            float4 bhi = *(const float4*)(W_val + (k + 1) * Cc + n0 + mf * 4);
            uint4 ub;
            ub.x = packbf(blo.x * g0, bhi.x * g1); ub.y = packbf(blo.y * g0, bhi.y * g1);
            ub.z = packbf(blo.z * g0, bhi.z * g1); ub.w = packbf(blo.w * g0, bhi.w * g1);
            *(uint4*)&Bs2[k2][mf * 4] = ub;
        }
        __syncthreads();
#pragma unroll
        for (int kk = 0; kk < 2; kk++) {
            int base = kk * 8;
            uint32_t a[4][4], bf[4][2];
#pragma unroll
            for (int mt = 0; mt < 4; mt++) {
                int r = warp_m * 64 + mt * 16 + lr;
                a[mt][0] = As2[base + lk][r];
                a[mt][1] = As2[base + lk][r + 8];
                a[mt][2] = As2[base + lk + 4][r];
                a[mt][3] = As2[base + lk + 4][r + 8];
            }
#pragma unroll
            for (int nt = 0; nt < 4; nt++) {
                int c = warp_n * 32 + nt * 8 + lr;
                bf[nt][0] = Bs2[base + lk][c];
                bf[nt][1] = Bs2[base + lk + 4][c];
            }
#pragma unroll
            for (int mt = 0; mt < 4; mt++)
#pragma unroll
                for (int nt = 0; nt < 4; nt++)
                    mma_bf16(acc[mt][nt], a[mt], bf[nt]);
        }
        __syncthreads();
    }

    int lc2 = (lane & 3) * 2;
#pragma unroll
    for (int mt = 0; mt < 4; mt++) {
        int q1 = m0 + warp_m * 64 + mt * 16 + lr;
        int q2 = q1 + 8;
        int g1 = b * NQ + q1, g2 = b * NQ + q2;
        float r1 = g_rstd2[g1], mm1 = r1 * g_mean2[g1];
        float r2 = g_rstd2[g2], mm2 = r2 * g_mean2[g2];
#pragma unroll
        for (int nt = 0; nt < 4; nt++) {
            int c = n0 + warp_n * 32 + nt * 8 + lc2;
            float vG0 = g_vG[c], vG1 = g_vG[c + 1];
            float vc0 = g_vc[c], vc1 = g_vc[c + 1];
            g_value[(size_t)g1 * 128 + (c >> 1)] =
                packbf(r1 * acc[mt][nt][0] - mm1 * vG0 + vc0,
                       r1 * acc[mt][nt][1] - mm1 * vG1 + vc1);
            g_value[(size_t)g2 * 128 + (c >> 1)] =
                packbf(r2 * acc[mt][nt][2] - mm2 * vG0 + vc0,
                       r2 * acc[mt][nt][3] - mm2 * vG1 + vc1);
        }
    }
}

// ---------------- K5: bilinear sampling — slim gather loop ----------------
__global__ void __launch_bounds__(512) k_sample()
{
    int tid = threadIdx.x;
    int warp = tid >> 5, lane = tid & 31;
    int b = blockIdx.y;
    int qg = blockIdx.x * 4 + (warp >> 2);
    int h = warp & 3;

    const uint2* __restrict__ pp = g_pairs + ((size_t)(b * NQ + qg) * 4 + h) * 16;
    const uint32_t* __restrict__ vbase = g_value + (size_t)b * NQ * 128 + h * 32 + lane;

    float a0 = 0.f, a1 = 0.f;
#pragma unroll
    for (int c = 0; c < 16; c++) {
        uint2 pr = pp[c];
        float w = __uint_as_float(pr.y);
        uint32_t v = vbase[(size_t)pr.x * 128];
        __nv_bfloat162 bv = *(__nv_bfloat162*)&v;
        a0 += w * __bfloat162float(bv.x);
        a1 += w * __bfloat162float(bv.y);
    }
    g_S[(size_t)(b * NQ + qg) * 128 + h * 32 + lane] = packbf(a0, a1);
}

// ---------------- K6: output GEMM (bf16 mma) ----------------
__global__ void __launch_bounds__(256, 2) k_gemm_out(const float* __restrict__ W_out,
                                                     const float* __restrict__ x2,
                                                     const float* __restrict__ b_out,
                                                     float* __restrict__ out)
{
    __shared__ uint32_t As2[16][136];
    __shared__ uint32_t Bs2[16][136];

    int b = blockIdx.z;
    int m0 = blockIdx.x * 128;      // c'
    int n0 = blockIdx.y * 128;      // q
    int tid = threadIdx.x;
    int wid = tid >> 5, lane = tid & 31;
    int warp_m = wid & 1, warp_n = wid >> 1;
    int lr = lane >> 2, lk = lane & 3;

    float acc[4][4][4];
#pragma unroll
    for (int i = 0; i < 4; i++)
#pragma unroll
        for (int j = 0; j < 4; j++)
#pragma unroll
            for (int r = 0; r < 4; r++) acc[i][j][r] = 0.f;

    const uint32_t* Sb = g_S + (size_t)(b * NQ + n0) * 128;

    for (int k0 = 0; k0 < Cc; k0 += 32) {
#pragma unroll
        for (int i = 0; i < 2; i++) {
            int lin = tid + i * 256;
            int k2 = lin >> 5, mf = lin & 31;
            int k = k0 + 2 * k2;
            float4 alo = *(const float4*)(W_out + k * Cc + m0 + mf * 4);
            float4 ahi = *(const float4*)(W_out + (k + 1) * Cc + m0 + mf * 4);
            uint4 u;
            u.x = packbf(alo.x, ahi.x); u.y = packbf(alo.y, ahi.y);
            u.z = packbf(alo.z, ahi.z); u.w = packbf(alo.w, ahi.w);
            *(uint4*)&As2[k2][mf * 4] = u;
        }
#pragma unroll
        for (int i = 0; i < 8; i++) {
            int lin = tid + i * 256;
            int k2 = lin & 15, q = lin >> 4;
            Bs2[k2][q] = Sb[(size_t)q * 128 + (k0 >> 1) + k2];
        }
        __syncthreads();
#pragma unroll
        for (int kk = 0; kk < 2; kk++) {
            int base = kk * 8;
            uint32_t a[4][4], bf[4][2];
#pragma unroll
            for (int mt = 0; mt < 4; mt++) {
                int r = warp_m * 64 + mt * 16 + lr;
                a[mt][0] = As2[base + lk][r];
                a[mt][1] = As2[base + lk][r + 8];
                a[mt][2] = As2[base + lk + 4][r];
                a[mt][3] = As2[base + lk + 4][r + 8];
            }
#pragma unroll
            for (int nt = 0; nt < 4; nt++) {
                int c = warp_n * 32 + nt * 8 + lr;
                bf[nt][0] = Bs2[base + lk][c];
                bf[nt][1] = Bs2[base + lk + 4][c];
            }
#pragma unroll
            for (int mt = 0; mt < 4; mt++)
#pragma unroll
                for (int nt = 0; nt < 4; nt++)
                    mma_bf16(acc[mt][nt], a[mt], bf[nt]);
        }
        __syncthreads();
    }

    int lc2 = (lane & 3) * 2;
#pragma unroll
    for (int mt = 0; mt < 4; mt++) {
        int c1 = m0 + warp_m * 64 + mt * 16 + lr;
        int c2 = c1 + 8;
        float bo1 = b_out[c1], bo2 = b_out[c2];
        size_t base1 = ((size_t)b * Cc + c1) * NQ;
        size_t base2 = ((size_t)b * Cc + c2) * NQ;
#pragma unroll
        for (int nt = 0; nt < 4; nt++) {
            int q = n0 + warp_n * 32 + nt * 8 + lc2;
            float2 x1v = *(const float2*)(x2 + base1 + q);
            float2 x2v = *(const float2*)(x2 + base2 + q);
            float2 o1, o2;
            o1.x = acc[mt][nt][0] + bo1 + x1v.x;
            o1.y = acc[mt][nt][1] + bo1 + x1v.y;
            o2.x = acc[mt][nt][2] + bo2 + x2v.x;
            o2.y = acc[mt][nt][3] + bo2 + x2v.y;
            *(float2*)(out + base1 + q) = o1;
            *(float2*)(out + base2 + q) = o2;
        }
    }
}

// ---------------- launch ----------------
extern "C" void kernel_launch(void* const* d_in, const int* in_sizes, int n_in,
                              void* d_out, int out_size)
{
    const float* x1        = (const float*)d_in[0];
    const float* x2        = (const float*)d_in[1];
    const float* ln1_g     = (const float*)d_in[2];
    const float* ln1_b     = (const float*)d_in[3];
    const float* ln2_g     = (const float*)d_in[4];
    const float* ln2_b     = (const float*)d_in[5];
    const float* pos_scale = (const float*)d_in[6];
    const float* W_off     = (const float*)d_in[7];
    const float* b_off     = (const float*)d_in[8];
    const float* W_att     = (const float*)d_in[9];
    const float* b_att     = (const float*)d_in[10];
    const float* W_val     = (const float*)d_in[11];
    const float* b_val     = (const float*)d_in[12];
    const float* W_out     = (const float*)d_in[13];
    const float* b_out     = (const float*)d_in[14];
    float* out = (float*)d_out;

    k_pre<<<257 + NQ, 256>>>(x1, x2, ln1_g, ln1_b, ln2_g, ln2_b, pos_scale,
                             W_off, b_off, W_att, b_att, W_val, b_val);
    k_offatt<<<dim3(NQ / 128, Bb), 256>>>(x1, W_off, W_att, ln1_g);
    k_gemm_val<<<dim3(Cc / 128, NQ / 128, Bb), 256>>>(x2, W_val, ln2_g);
    k_sample<<<dim3(NQ / 4, Bb), 512>>>();
    k_gemm_out<<<dim3(Cc / 128, NQ / 128, Bb), 256>>>(W_out, x2, b_out, out);
}

// round 5
// speedup vs baseline: 2.6992x; 1.0592x over previous
#include <cuda_runtime.h>
#include <cuda_bf16.h>
#include <math.h>
#include <stdint.h>

// Problem constants
#define Bb   8
#define Cc   256
#define Hh   64
#define Ww   64
#define NQ   4096           // H*W
#define NPIX (Bb*NQ)        // 32768
#define NHh  4
#define NPp  4
#define Dd   64
#define EPSf 1e-5f

// ---------------- scratch (static device globals; no allocation) ----------------
__device__ float g_mean1[NPIX], g_rstd1[NPIX], g_mean2[NPIX], g_rstd2[NPIX];
__device__ float g_qp[NQ * 48];          // qpos @ [W_off | W_att]
__device__ float g_c48[48];              // b + ln1_b @ W
__device__ float g_gs48[48];             // ln1_g @ W
__device__ float g_vG[Cc];               // ln2_g @ W_val
__device__ float g_vc[Cc];               // b_val + ln2_b @ W_val
__device__ uint32_t g_value[NPIX * Cc / 2];  // bf16x2: (B,Nq,C), pair (c, c+1)
__device__ uint2 g_pairs[(size_t)NPIX * 64]; // per (b,q,h): 16 x (byte offset, weight)
__device__ uint32_t g_S[NPIX * Cc / 2];      // bf16x2 sampled output (B,Nq,C)

// ---------------- helpers ----------------
__device__ __forceinline__ uint32_t packbf(float lo, float hi)
{
    __nv_bfloat162 h = __floats2bfloat162_rn(lo, hi);
    return *(uint32_t*)&h;
}

__device__ __forceinline__ void mma_bf16(float* d, const uint32_t* a, const uint32_t* b)
{
    asm volatile(
        "mma.sync.aligned.m16n8k16.row.col.f32.bf16.bf16.f32 "
        "{%0,%1,%2,%3}, {%4,%5,%6,%7}, {%8,%9}, {%0,%1,%2,%3};\n"
        : "+f"(d[0]), "+f"(d[1]), "+f"(d[2]), "+f"(d[3])
        : "r"(a[0]), "r"(a[1]), "r"(a[2]), "r"(a[3]), "r"(b[0]), "r"(b[1]));
}

// ---------------- K_pre: const + stats + qpos, one launch ----------------
__global__ void __launch_bounds__(256) k_pre(
    const float* __restrict__ x1, const float* __restrict__ x2,
    const float* __restrict__ ln1_g, const float* __restrict__ ln1_b,
    const float* __restrict__ ln2_g, const float* __restrict__ ln2_b,
    const float* __restrict__ pos_scale,
    const float* __restrict__ W_off, const float* __restrict__ b_off,
    const float* __restrict__ W_att, const float* __restrict__ b_att,
    const float* __restrict__ W_val, const float* __restrict__ b_val)
{
    int bid = blockIdx.x;
    int tid = threadIdx.x;

    if (bid == 0) {
        float sG = 0.f, sc = 0.f;
        for (int k = 0; k < Cc; k++) {
            float w = W_val[k * Cc + tid];
            sG += ln2_g[k] * w;
            sc += ln2_b[k] * w;
        }
        g_vG[tid] = sG;
        g_vc[tid] = sc + b_val[tid];

        if (tid < 48) {
            float s1 = 0.f, s2 = 0.f, bb;
            if (tid < 32) {
                for (int k = 0; k < Cc; k++) {
                    float w = W_off[k * 32 + tid];
                    s1 += ln1_b[k] * w;
                    s2 += ln1_g[k] * w;
                }
                bb = b_off[tid];
            } else {
                int j = tid - 32;
                for (int k = 0; k < Cc; k++) {
                    float w = W_att[k * 16 + j];
                    s1 += ln1_b[k] * w;
                    s2 += ln1_g[k] * w;
                }
                bb = b_att[j];
            }
            g_c48[tid] = s1 + bb;
            g_gs48[tid] = s2;
        }
    } else if (bid <= 256) {
        int t = (bid - 1) * 256 + tid;          // 0 .. 2*NPIX-1
        int idx = t & (NPIX - 1);
        const float* x = (t < NPIX) ? x1 : x2;
        const float* p = x + (idx >> 12) * (Cc * NQ) + (idx & (NQ - 1));
        float s = 0.f, ss = 0.f;
#pragma unroll 8
        for (int k = 0; k < Cc; k++) {
            float v = p[k * NQ];
            s += v;
            ss += v * v;
        }
        float m = s * (1.0f / Cc);
        float var = ss * (1.0f / Cc) - m * m;
        float r = rsqrtf(var + EPSf);
        if (t < NPIX) { g_mean1[idx] = m; g_rstd1[idx] = r; }
        else          { g_mean2[idx] = m; g_rstd2[idx] = r; }
    } else {
        __shared__ float qp[Cc];
        int q = bid - 257;
        float ps = pos_scale[0];
        {
            int k = tid;
            int i = (k < 128) ? k : k - 128;
            float invf = expf(-9.210340371976184f * (float)i * (1.0f / 128.0f));
            float ang = (float)q * invf;
            qp[k] = ((k < 128) ? sinf(ang) : cosf(ang)) * ps;
        }
        __syncthreads();
        if (tid < 192) {
            int j = tid >> 2;
            int part = tid & 3;
            float s = 0.f;
            int kk0 = part * 64;
            if (j < 32) {
                for (int k = kk0; k < kk0 + 64; k++) s += qp[k] * W_off[k * 32 + j];
            } else {
                int jj = j - 32;
                for (int k = kk0; k < kk0 + 64; k++) s += qp[k] * W_att[k * 16 + jj];
            }
            s += __shfl_xor_sync(0xFFFFFFFFu, s, 1);
            s += __shfl_xor_sync(0xFFFFFFFFu, s, 2);
            if (part == 0) g_qp[q * 48 + j] = s;
        }
    }
}

// ---------------- K3: off/att GEMM (bf16 mma) + softmax + sampler-operand precompute ----------------
__global__ void __launch_bounds__(256, 2) k_offatt(const float* __restrict__ x1,
                                                   const float* __restrict__ W_off,
                                                   const float* __restrict__ W_att,
                                                   const float* __restrict__ ln1_g)
{
    __shared__ uint32_t As2[16][136];
    __shared__ uint32_t Bs2[16][72];
    __shared__ float Out[128][52];

    int b = blockIdx.y;
    int q0 = blockIdx.x * 128;
    int tid = threadIdx.x;
    int wid = tid >> 5, lane = tid & 31;
    int warp_m = wid & 1, warp_n = wid >> 1;
    int lr = lane >> 2, lk = lane & 3;

    float acc[4][2][4];
#pragma unroll
    for (int i = 0; i < 4; i++)
#pragma unroll
        for (int j = 0; j < 2; j++)
#pragma unroll
            for (int r = 0; r < 4; r++) acc[i][j][r] = 0.f;

    const float* Ab = x1 + b * (Cc * NQ) + q0;

    for (int k0 = 0; k0 < Cc; k0 += 32) {
#pragma unroll
        for (int i = 0; i < 2; i++) {
            int lin = tid + i * 256;
            int k2 = lin >> 5, mf = lin & 31;
            float4 alo = *(const float4*)(Ab + (k0 + 2 * k2) * NQ + mf * 4);
            float4 ahi = *(const float4*)(Ab + (k0 + 2 * k2 + 1) * NQ + mf * 4);
            uint4 u;
            u.x = packbf(alo.x, ahi.x); u.y = packbf(alo.y, ahi.y);
            u.z = packbf(alo.z, ahi.z); u.w = packbf(alo.w, ahi.w);
            *(uint4*)&As2[k2][mf * 4] = u;
        }
#pragma unroll
        for (int i = 0; i < 4; i++) {
            int lin = tid + i * 256;
            int j = lin & 63;
            int k2 = lin >> 6;
            int k = k0 + 2 * k2;
            float lo = 0.f, hi = 0.f;
            if (j < 32) {
                lo = W_off[k * 32 + j] * ln1_g[k];
                hi = W_off[(k + 1) * 32 + j] * ln1_g[k + 1];
            } else if (j < 48) {
                int jj = j - 32;
                lo = W_att[k * 16 + jj] * ln1_g[k];
                hi = W_att[(k + 1) * 16 + jj] * ln1_g[k + 1];
            }
            Bs2[k2][j] = packbf(lo, hi);
        }
        __syncthreads();
#pragma unroll
        for (int kk = 0; kk < 2; kk++) {
            int base = kk * 8;
            uint32_t a[4][4], bf[2][2];
#pragma unroll
            for (int mt = 0; mt < 4; mt++) {
                int r = warp_m * 64 + mt * 16 + lr;
                a[mt][0] = As2[base + lk][r];
                a[mt][1] = As2[base + lk][r + 8];
                a[mt][2] = As2[base + lk + 4][r];
                a[mt][3] = As2[base + lk + 4][r + 8];
            }
#pragma unroll
            for (int nt = 0; nt < 2; nt++) {
                int c = warp_n * 16 + nt * 8 + lr;
                bf[nt][0] = Bs2[base + lk][c];
                bf[nt][1] = Bs2[base + lk + 4][c];
            }
#pragma unroll
            for (int mt = 0; mt < 4; mt++)
#pragma unroll
                for (int nt = 0; nt < 2; nt++)
                    mma_bf16(acc[mt][nt], a[mt], bf[nt]);
        }
        __syncthreads();
    }

    int lc2 = (lane & 3) * 2;
#pragma unroll
    for (int mt = 0; mt < 4; mt++) {
#pragma unroll
        for (int nt = 0; nt < 2; nt++) {
            int c = warp_n * 16 + nt * 8 + lc2;
            if (c < 48) {
                int r = warp_m * 64 + mt * 16 + lr;
                *(float2*)&Out[r][c]     = make_float2(acc[mt][nt][0], acc[mt][nt][1]);
                *(float2*)&Out[r + 8][c] = make_float2(acc[mt][nt][2], acc[mt][nt][3]);
            }
        }
    }
    __syncthreads();

    if (tid < 128) {
        int qg = q0 + tid;
        int gidx = b * NQ + qg;
        float r = g_rstd1[gidx];
        float mterm = r * g_mean1[gidx];
        float vals[48];
#pragma unroll
        for (int j = 0; j < 48; j++)
            vals[j] = r * Out[tid][j] - mterm * g_gs48[j] + g_c48[j] + g_qp[qg * 48 + j];

        float wpix = (float)(qg & 63);
        float hpix = (float)(qg >> 6);
#pragma unroll
        for (int h = 0; h < NHh; h++) {
            float* av = &vals[32 + h * 4];
            float mx = fmaxf(fmaxf(av[0], av[1]), fmaxf(av[2], av[3]));
            float e0 = __expf(av[0] - mx), e1 = __expf(av[1] - mx);
            float e2 = __expf(av[2] - mx), e3 = __expf(av[3] - mx);
            float inv = 1.0f / (e0 + e1 + e2 + e3);
            float aw[4] = {e0 * inv, e1 * inv, e2 * inv, e3 * inv};

            uint2* pp = g_pairs + ((size_t)gidx * 4 + h) * 16;
#pragma unroll
            for (int p = 0; p < NPp; p++) {
                float px = wpix + vals[h * 8 + p * 2];
                float py = hpix + vals[h * 8 + p * 2 + 1];
                float fx = floorf(px), fy = floorf(py);
                int ix = (int)fx, iy = (int)fy;
                float wx = px - fx, wy = py - fy;
                float a = aw[p];
                uint4 st0, st1;
#pragma unroll
                for (int c = 0; c < 4; c++) {
                    int cx = ix + (c & 1);
                    int cy = iy + (c >> 1);
                    bool valid = (cx >= 0) & (cx < Ww) & (cy >= 0) & (cy < Hh);
                    float wgt = valid ? ((c & 1) ? wx : 1.f - wx) * ((c >> 1) ? wy : 1.f - wy) * a : 0.f;
                    // byte offset into g_value row space: pixel * (Cc/2 uint32 * 4B) = pixel * 512
                    uint32_t off = valid ? (uint32_t)(cy * Ww + cx) * 512u : 0u;
                    if (c == 0) { st0.x = off; st0.y = __float_as_uint(wgt); }
                    if (c == 1) { st0.z = off; st0.w = __float_as_uint(wgt); }
                    if (c == 2) { st1.x = off; st1.y = __float_as_uint(wgt); }
                    if (c == 3) { st1.z = off; st1.w = __float_as_uint(wgt); }
                }
                *(uint4*)&pp[p * 4]     = st0;
                *(uint4*)&pp[p * 4 + 2] = st1;
            }
        }
    }
}

// ---------------- K4: value GEMM (bf16 mma) -> g_value bf16 ----------------
__global__ void __launch_bounds__(256, 2) k_gemm_val(const float* __restrict__ x2,
                                                     const float* __restrict__ W_val,
                                                     const float* __restrict__ ln2_g)
{
    __shared__ uint32_t As2[16][136];
    __shared__ uint32_t Bs2[16][136];

    int b = blockIdx.z;
    int n0 = blockIdx.x * 128;
    int m0 = blockIdx.y * 128;
    int tid = threadIdx.x;
    int wid = tid >> 5, lane = tid & 31;
    int warp_m = wid & 1, warp_n = wid >> 1;
    int lr = lane >> 2, lk = lane & 3;

    float acc[4][4][4];
#pragma unroll
    for (int i = 0; i < 4; i++)
#pragma unroll
        for (int j = 0; j < 4; j++)
#pragma unroll
            for (int r = 0; r < 4; r++) acc[i][j][r] = 0.f;

    const float* Ab = x2 + b * (Cc * NQ) + m0;

    for (int k0 = 0; k0 < Cc; k0 += 32) {
#pragma unroll
        for (int i = 0; i < 2; i++) {
            int lin = tid + i * 256;
            int k2 = lin >> 5, mf = lin & 31;
            int k = k0 + 2 * k2;
            float4 alo = *(const float4*)(Ab + k * NQ + mf * 4);
            float4 ahi = *(const float4*)(Ab + (k + 1) * NQ + mf * 4);
            uint4 ua;
            ua.x = packbf(alo.x, ahi.x); ua.y = packbf(alo.y, ahi.y);
            ua.z = packbf(alo.z, ahi.z); ua.w = packbf(alo.w, ahi.w);
            *(uint4*)&As2[k2][mf * 4] = ua;
            float g0 = ln2_g[k], g1 = ln2_g[k + 1];
            float4 blo = *(const float4*)(W_val + k * Cc + n0 + mf * 4);
            float4 bhi = *(const float4*)(W_val + (k + 1) * Cc + n0 + mf * 4);
            uint4 ub;
            ub.x = packbf(blo.x * g0, bhi.x * g1); ub.y = packbf(blo.y * g0, bhi.y * g1);
            ub.z = packbf(blo.z * g0, bhi.z * g1); ub.w = packbf(blo.w * g0, bhi.w * g1);
            *(uint4*)&Bs2[k2][mf * 4] = ub;
        }
        __syncthreads();
#pragma unroll
        for (int kk = 0; kk < 2; kk++) {
            int base = kk * 8;
            uint32_t a[4][4], bf[4][2];
#pragma unroll
            for (int mt = 0; mt < 4; mt++) {
                int r = warp_m * 64 + mt * 16 + lr;
                a[mt][0] = As2[base + lk][r];
                a[mt][1] = As2[base + lk][r + 8];
                a[mt][2] = As2[base + lk + 4][r];
                a[mt][3] = As2[base + lk + 4][r + 8];
            }
#pragma unroll
            for (int nt = 0; nt < 4; nt++) {
                int c = warp_n * 32 + nt * 8 + lr;
                bf[nt][0] = Bs2[base + lk][c];
                bf[nt][1] = Bs2[base + lk + 4][c];
            }
#pragma unroll
            for (int mt = 0; mt < 4; mt++)
#pragma unroll
                for (int nt = 0; nt < 4; nt++)
                    mma_bf16(acc[mt][nt], a[mt], bf[nt]);
        }
        __syncthreads();
    }

    int lc2 = (lane & 3) * 2;
#pragma unroll
    for (int mt = 0; mt < 4; mt++) {
        int q1 = m0 + warp_m * 64 + mt * 16 + lr;
        int q2 = q1 + 8;
        int g1 = b * NQ + q1, g2 = b * NQ + q2;
        float r1 = g_rstd2[g1], mm1 = r1 * g_mean2[g1];
        float r2 = g_rstd2[g2], mm2 = r2 * g_mean2[g2];
#pragma unroll
        for (int nt = 0; nt < 4; nt++) {
            int c = n0 + warp_n * 32 + nt * 8 + lc2;
            float vG0 = g_vG[c], vG1 = g_vG[c + 1];
            float vc0 = g_vc[c], vc1 = g_vc[c + 1];
            g_value[(size_t)g1 * 128 + (c >> 1)] =
                packbf(r1 * acc[mt][nt][0] - mm1 * vG0 + vc0,
                       r1 * acc[mt][nt][1] - mm1 * vG1 + vc1);
            g_value[(size_t)g2 * 128 + (c >> 1)] =
                packbf(r2 * acc[mt][nt][2] - mm2 * vG0 + vc0,
                       r2 * acc[mt][nt][3] - mm2 * vG1 + vc1);
        }
    }
}

// ---------------- K5: bilinear sampling — warp covers (q, 2 heads), lane = 4 channels ----------------
__global__ void __launch_bounds__(512) k_sample()
{
    int tid = threadIdx.x;
    int warp = tid >> 5, lane = tid & 31;
    int b = blockIdx.y;
    int qg = blockIdx.x * 8 + (warp >> 1);
    int hl = (warp & 1) * 2 + (lane >> 4);   // this lane's head
    int sub = lane & 15;                     // channel group within head (4 ch)

    // one pair per lane (16 pairs per head, segmented per half-warp), then shfl-broadcast
    const uint2* __restrict__ pp = g_pairs + ((size_t)(b * NQ + qg) * 4 + hl) * 16;
    uint2 pr = pp[sub];

    const char* __restrict__ vbase =
        (const char*)g_value + (size_t)b * NQ * 512 + hl * 128 + sub * 8;

    float a0 = 0.f, a1 = 0.f, a2 = 0.f, a3 = 0.f;
#pragma unroll
    for (int c = 0; c < 16; c++) {
        uint32_t ob = __shfl_sync(0xFFFFFFFFu, pr.x, c, 16);
        float w = __uint_as_float(__shfl_sync(0xFFFFFFFFu, pr.y, c, 16));
        uint2 v = *(const uint2*)(vbase + ob);
        float v0 = __uint_as_float(v.x << 16);
        float v1 = __uint_as_float(v.x & 0xFFFF0000u);
        float v2 = __uint_as_float(v.y << 16);
        float v3 = __uint_as_float(v.y & 0xFFFF0000u);
        a0 += w * v0; a1 += w * v1; a2 += w * v2; a3 += w * v3;
    }
    uint2 st;
    st.x = packbf(a0, a1);
    st.y = packbf(a2, a3);
    *(uint2*)((char*)g_S + (size_t)(b * NQ + qg) * 512 + hl * 128 + sub * 8) = st;
}

// ---------------- K6: output GEMM (bf16 mma) ----------------
__global__ void __launch_bounds__(256, 2) k_gemm_out(const float* __restrict__ W_out,
                                                     const float* __restrict__ x2,
                                                     const float* __restrict__ b_out,
                                                     float* __restrict__ out)
{
    __shared__ uint32_t As2[16][136];
    __shared__ uint32_t Bs2[16][136];

    int b = blockIdx.z;
    int m0 = blockIdx.x * 128;      // c'
    int n0 = blockIdx.y * 128;      // q
    int tid = threadIdx.x;
    int wid = tid >> 5, lane = tid & 31;
    int warp_m = wid & 1, warp_n = wid >> 1;
    int lr = lane >> 2, lk = lane & 3;

    float acc[4][4][4];
#pragma unroll
    for (int i = 0; i < 4; i++)
#pragma unroll
        for (int j = 0; j < 4; j++)
#pragma unroll
            for (int r = 0; r < 4; r++) acc[i][j][r] = 0.f;

    const uint32_t* Sb = g_S + (size_t)(b * NQ + n0) * 128;

    for (int k0 = 0; k0 < Cc; k0 += 32) {
#pragma unroll
        for (int i = 0; i < 2; i++) {
            int lin = tid + i * 256;
            int k2 = lin >> 5, mf = lin & 31;
            int k = k0 + 2 * k2;
            float4 alo = *(const float4*)(W_out + k * Cc + m0 + mf * 4);
            float4 ahi = *(const float4*)(W_out + (k + 1) * Cc + m0 + mf * 4);
            uint4 u;
            u.x = packbf(alo.x, ahi.x); u.y = packbf(alo.y, ahi.y);
            u.z = packbf(alo.z, ahi.z); u.w = packbf(alo.w, ahi.w);
            *(uint4*)&As2[k2][mf * 4] = u;
        }
#pragma unroll
        for (int i = 0; i < 8; i++) {
            int lin = tid + i * 256;
            int k2 = lin & 15, q = lin >> 4;
            Bs2[k2][q] = Sb[(size_t)q * 128 + (k0 >> 1) + k2];
        }
        __syncthreads();
#pragma unroll
        for (int kk = 0; kk < 2; kk++) {
            int base = kk * 8;
            uint32_t a[4][4], bf[4][2];
#pragma unroll
            for (int mt = 0; mt < 4; mt++) {
                int r = warp_m * 64 + mt * 16 + lr;
                a[mt][0] = As2[base + lk][r];
                a[mt][1] = As2[base + lk][r + 8];
                a[mt][2] = As2[base + lk + 4][r];
                a[mt][3] = As2[base + lk + 4][r + 8];
            }
#pragma unroll
            for (int nt = 0; nt < 4; nt++) {
                int c = warp_n * 32 + nt * 8 + lr;
                bf[nt][0] = Bs2[base + lk][c];
                bf[nt][1] = Bs2[base + lk + 4][c];
            }
#pragma unroll
            for (int mt = 0; mt < 4; mt++)
#pragma unroll
                for (int nt = 0; nt < 4; nt++)
                    mma_bf16(acc[mt][nt], a[mt], bf[nt]);
        }
        __syncthreads();
    }

    int lc2 = (lane & 3) * 2;
#pragma unroll
    for (int mt = 0; mt < 4; mt++) {
        int c1 = m0 + warp_m * 64 + mt * 16 + lr;
        int c2 = c1 + 8;
        float bo1 = b_out[c1], bo2 = b_out[c2];
        size_t base1 = ((size_t)b * Cc + c1) * NQ;
        size_t base2 = ((size_t)b * Cc + c2) * NQ;
#pragma unroll
        for (int nt = 0; nt < 4; nt++) {
            int q = n0 + warp_n * 32 + nt * 8 + lc2;
            float2 x1v = *(const float2*)(x2 + base1 + q);
            float2 x2v = *(const float2*)(x2 + base2 + q);
            float2 o1, o2;
            o1.x = acc[mt][nt][0] + bo1 + x1v.x;
            o1.y = acc[mt][nt][1] + bo1 + x1v.y;
            o2.x = acc[mt][nt][2] + bo2 + x2v.x;
            o2.y = acc[mt][nt][3] + bo2 + x2v.y;
            *(float2*)(out + base1 + q) = o1;
            *(float2*)(out + base2 + q) = o2;
        }
    }
}

// ---------------- launch ----------------
extern "C" void kernel_launch(void* const* d_in, const int* in_sizes, int n_in,
                              void* d_out, int out_size)
{
    const float* x1        = (const float*)d_in[0];
    const float* x2        = (const float*)d_in[1];
    const float* ln1_g     = (const float*)d_in[2];
    const float* ln1_b     = (const float*)d_in[3];
    const float* ln2_g     = (const float*)d_in[4];
    const float* ln2_b     = (const float*)d_in[5];
    const float* pos_scale = (const float*)d_in[6];
    const float* W_off     = (const float*)d_in[7];
    const float* b_off     = (const float*)d_in[8];
    const float* W_att     = (const float*)d_in[9];
    const float* b_att     = (const float*)d_in[10];
    const float* W_val     = (const float*)d_in[11];
    const float* b_val     = (const float*)d_in[12];
    const float* W_out     = (const float*)d_in[13];
    const float* b_out     = (const float*)d_in[14];
    float* out = (float*)d_out;

    k_pre<<<257 + NQ, 256>>>(x1, x2, ln1_g, ln1_b, ln2_g, ln2_b, pos_scale,
                             W_off, b_off, W_att, b_att, W_val, b_val);
    k_offatt<<<dim3(NQ / 128, Bb), 256>>>(x1, W_off, W_att, ln1_g);
    k_gemm_val<<<dim3(Cc / 128, NQ / 128, Bb), 256>>>(x2, W_val, ln2_g);
    k_sample<<<dim3(NQ / 8, Bb), 512>>>();
    k_gemm_out<<<dim3(Cc / 128, NQ / 128, Bb), 256>>>(W_out, x2, b_out, out);
}

// round 6
// speedup vs baseline: 2.9138x; 1.0795x over previous
#include <cuda_runtime.h>
#include <cuda_bf16.h>
#include <math.h>
#include <stdint.h>

// Problem constants
#define Bb   8
#define Cc   256
#define Hh   64
#define Ww   64
#define NQ   4096           // H*W
#define NPIX (Bb*NQ)        // 32768
#define NHh  4
#define NPp  4
#define Dd   64
#define EPSf 1e-5f

// ---------------- scratch (static device globals; no allocation) ----------------
__device__ float g_mean1[NPIX], g_rstd1[NPIX], g_mean2[NPIX], g_rstd2[NPIX];
__device__ float g_qp[NQ * 48];          // qpos @ [W_off | W_att]
__device__ float g_c48[48];              // b + ln1_b @ W
__device__ float g_gs48[48];             // ln1_g @ W
__device__ float g_vG[Cc];               // ln2_g @ W_val
__device__ float g_vc[Cc];               // b_val + ln2_b @ W_val
__device__ uint32_t g_x1b[(size_t)NPIX * 128];  // bf16x2 pack of x1: [b][k2][q]
__device__ uint32_t g_x2b[(size_t)NPIX * 128];  // bf16x2 pack of x2: [b][k2][q]
__device__ uint32_t g_Wvb[128 * 256];    // bf16x2 (ln2_g-scaled W_val): [k2][n]
__device__ uint32_t g_Wob[128 * 256];    // bf16x2 W_out: [k2][m]
__device__ uint32_t g_Wqb[128 * 64];     // bf16x2 (ln1_g-scaled [W_off|W_att|0]): [k2][j]
__device__ uint32_t g_value[NPIX * Cc / 2];  // bf16x2: (B,Nq,C), pair (c, c+1)
__device__ uint2 g_pairs[(size_t)NPIX * 64]; // per (b,q,h): 16 x (byte offset, weight)
__device__ uint32_t g_S[NPIX * Cc / 2];      // bf16x2 sampled output (B,Nq,C)

// ---------------- helpers ----------------
__device__ __forceinline__ uint32_t packbf(float lo, float hi)
{
    __nv_bfloat162 h = __floats2bfloat162_rn(lo, hi);
    return *(uint32_t*)&h;
}

__device__ __forceinline__ void mma_bf16(float* d, const uint32_t* a, const uint32_t* b)
{
    asm volatile(
        "mma.sync.aligned.m16n8k16.row.col.f32.bf16.bf16.f32 "
        "{%0,%1,%2,%3}, {%4,%5,%6,%7}, {%8,%9}, {%0,%1,%2,%3};\n"
        : "+f"(d[0]), "+f"(d[1]), "+f"(d[2]), "+f"(d[3])
        : "r"(a[0]), "r"(a[1]), "r"(a[2]), "r"(a[3]), "r"(b[0]), "r"(b[1]));
}

__device__ __forceinline__ void cp16(void* smem_dst, const void* gmem_src)
{
    uint32_t sa = (uint32_t)__cvta_generic_to_shared(smem_dst);
    asm volatile("cp.async.cg.shared.global [%0], [%1], 16;\n" :: "r"(sa), "l"(gmem_src));
}
#define CP_COMMIT() asm volatile("cp.async.commit_group;\n" ::: "memory")
#define CP_WAIT1()  asm volatile("cp.async.wait_group 1;\n" ::: "memory")
#define CP_WAIT0()  asm volatile("cp.async.wait_group 0;\n" ::: "memory")

// ---------------- K_pre: const + stats/pack + qpos + weight packs, one launch ----------------
// grid: 0 = const; 1..256 = stats+x-pack; 257..4352 = qp; 4353..4360 = Wval/Wout pack; 4361 = Wq pack
__global__ void __launch_bounds__(256) k_pre(
    const float* __restrict__ x1, const float* __restrict__ x2,
    const float* __restrict__ ln1_g, const float* __restrict__ ln1_b,
    const float* __restrict__ ln2_g, const float* __restrict__ ln2_b,
    const float* __restrict__ pos_scale,
    const float* __restrict__ W_off, const float* __restrict__ b_off,
    const float* __restrict__ W_att, const float* __restrict__ b_att,
    const float* __restrict__ W_val, const float* __restrict__ b_val,
    const float* __restrict__ W_out)
{
    int bid = blockIdx.x;
    int tid = threadIdx.x;

    if (bid == 0) {
        float sG = 0.f, sc = 0.f;
        for (int k = 0; k < Cc; k++) {
            float w = W_val[k * Cc + tid];
            sG += ln2_g[k] * w;
            sc += ln2_b[k] * w;
        }
        g_vG[tid] = sG;
        g_vc[tid] = sc + b_val[tid];

        if (tid < 48) {
            float s1 = 0.f, s2 = 0.f, bb;
            if (tid < 32) {
                for (int k = 0; k < Cc; k++) {
                    float w = W_off[k * 32 + tid];
                    s1 += ln1_b[k] * w;
                    s2 += ln1_g[k] * w;
                }
                bb = b_off[tid];
            } else {
                int j = tid - 32;
                for (int k = 0; k < Cc; k++) {
                    float w = W_att[k * 16 + j];
                    s1 += ln1_b[k] * w;
                    s2 += ln1_g[k] * w;
                }
                bb = b_att[j];
            }
            g_c48[tid] = s1 + bb;
            g_gs48[tid] = s2;
        }
    } else if (bid <= 256) {
        int t = (bid - 1) * 256 + tid;          // 0 .. 2*NPIX-1
        int idx = t & (NPIX - 1);
        int b = idx >> 12, q = idx & (NQ - 1);
        const float* p = ((t < NPIX) ? x1 : x2) + b * (Cc * NQ) + q;
        uint32_t* xb = ((t < NPIX) ? g_x1b : g_x2b) + (size_t)(b * 128) * NQ + q;
        float s = 0.f, ss = 0.f;
#pragma unroll 4
        for (int k2 = 0; k2 < 128; k2++) {
            float v0 = p[(2 * k2) * NQ];
            float v1 = p[(2 * k2 + 1) * NQ];
            s += v0 + v1;
            ss += v0 * v0 + v1 * v1;
            xb[(size_t)k2 * NQ] = packbf(v0, v1);
        }
        float m = s * (1.0f / Cc);
        float var = ss * (1.0f / Cc) - m * m;
        float r = rsqrtf(var + EPSf);
        if (t < NPIX) { g_mean1[idx] = m; g_rstd1[idx] = r; }
        else          { g_mean2[idx] = m; g_rstd2[idx] = r; }
    } else if (bid <= 4352) {
        __shared__ float qp[Cc];
        int q = bid - 257;
        float ps = pos_scale[0];
        {
            int k = tid;
            int i = (k < 128) ? k : k - 128;
            float invf = expf(-9.210340371976184f * (float)i * (1.0f / 128.0f));
            float ang = (float)q * invf;
            qp[k] = ((k < 128) ? sinf(ang) : cosf(ang)) * ps;
        }
        __syncthreads();
        if (tid < 192) {
            int j = tid >> 2;
            int part = tid & 3;
            float s = 0.f;
            int kk0 = part * 64;
            if (j < 32) {
                for (int k = kk0; k < kk0 + 64; k++) s += qp[k] * W_off[k * 32 + j];
            } else {
                int jj = j - 32;
                for (int k = kk0; k < kk0 + 64; k++) s += qp[k] * W_att[k * 16 + jj];
            }
            s += __shfl_xor_sync(0xFFFFFFFFu, s, 1);
            s += __shfl_xor_sync(0xFFFFFFFFu, s, 2);
            if (part == 0) g_qp[q * 48 + j] = s;
        }
    } else if (bid <= 4360) {
        int wb = bid - 4353;                    // 0..7
        if (wb < 4) {
#pragma unroll 4
            for (int r = 0; r < 32; r++) {
                int k2 = wb * 32 + r;
                int k = 2 * k2;
                float g0 = ln2_g[k], g1 = ln2_g[k + 1];
                g_Wvb[k2 * 256 + tid] = packbf(W_val[k * 256 + tid] * g0,
                                               W_val[(k + 1) * 256 + tid] * g1);
            }
        } else {
#pragma unroll 4
            for (int r = 0; r < 32; r++) {
                int k2 = (wb - 4) * 32 + r;
                int k = 2 * k2;
                g_Wob[k2 * 256 + tid] = packbf(W_out[k * 256 + tid],
                                               W_out[(k + 1) * 256 + tid]);
            }
        }
    } else {
#pragma unroll 4
        for (int i = 0; i < 32; i++) {
            int lin = i * 256 + tid;            // 8192
            int k2 = lin >> 6, j = lin & 63;
            int k = 2 * k2;
            float lo = 0.f, hi = 0.f;
            if (j < 32) {
                lo = W_off[k * 32 + j] * ln1_g[k];
                hi = W_off[(k + 1) * 32 + j] * ln1_g[k + 1];
            } else if (j < 48) {
                int jj = j - 32;
                lo = W_att[k * 16 + jj] * ln1_g[k];
                hi = W_att[(k + 1) * 16 + jj] * ln1_g[k + 1];
            }
            g_Wqb[k2 * 64 + j] = packbf(lo, hi);
        }
    }
}

// ---------------- K3: off/att GEMM (bf16 mma, packed operands) + softmax + pair precompute ----------------
__global__ void __launch_bounds__(256, 2) k_offatt(const float* __restrict__ dummy)
{
    __shared__ uint32_t As2[16][136];
    __shared__ uint32_t Bs2[16][72];
    __shared__ float Out[128][52];

    int b = blockIdx.y;
    int q0 = blockIdx.x * 128;
    int tid = threadIdx.x;
    int wid = tid >> 5, lane = tid & 31;
    int warp_m = wid & 1, warp_n = wid >> 1;
    int lr = lane >> 2, lk = lane & 3;

    float acc[4][2][4];
#pragma unroll
    for (int i = 0; i < 4; i++)
#pragma unroll
        for (int j = 0; j < 2; j++)
#pragma unroll
            for (int r = 0; r < 4; r++) acc[i][j][r] = 0.f;

    const uint32_t* Ab = g_x1b + (size_t)(b * 128) * NQ + q0;

    for (int k0 = 0; k0 < Cc; k0 += 32) {
        int k2b = k0 >> 1;
#pragma unroll
        for (int i = 0; i < 2; i++) {
            int lin = tid + i * 256;            // 512 uint4
            int row = lin >> 5, seg = lin & 31;
            *(uint4*)&As2[row][seg * 4] = *(const uint4*)(Ab + (size_t)(k2b + row) * NQ + seg * 4);
        }
        {
            int row = tid >> 4, seg = tid & 15;  // 256 uint4 = 16x64
            *(uint4*)&Bs2[row][seg * 4] = *(const uint4*)(g_Wqb + (k2b + row) * 64 + seg * 4);
        }
        __syncthreads();
#pragma unroll
        for (int kk = 0; kk < 2; kk++) {
            int base = kk * 8;
            uint32_t a[4][4], bf[2][2];
#pragma unroll
            for (int mt = 0; mt < 4; mt++) {
                int r = warp_m * 64 + mt * 16 + lr;
                a[mt][0] = As2[base + lk][r];
                a[mt][1] = As2[base + lk][r + 8];
                a[mt][2] = As2[base + lk + 4][r];
                a[mt][3] = As2[base + lk + 4][r + 8];
            }
#pragma unroll
            for (int nt = 0; nt < 2; nt++) {
                int c = warp_n * 16 + nt * 8 + lr;
                bf[nt][0] = Bs2[base + lk][c];
                bf[nt][1] = Bs2[base + lk + 4][c];
            }
#pragma unroll
            for (int mt = 0; mt < 4; mt++)
#pragma unroll
                for (int nt = 0; nt < 2; nt++)
                    mma_bf16(acc[mt][nt], a[mt], bf[nt]);
        }
        __syncthreads();
    }

    int lc2 = (lane & 3) * 2;
#pragma unroll
    for (int mt = 0; mt < 4; mt++) {
#pragma unroll
        for (int nt = 0; nt < 2; nt++) {
            int c = warp_n * 16 + nt * 8 + lc2;
            if (c < 48) {
                int r = warp_m * 64 + mt * 16 + lr;
                *(float2*)&Out[r][c]     = make_float2(acc[mt][nt][0], acc[mt][nt][1]);
                *(float2*)&Out[r + 8][c] = make_float2(acc[mt][nt][2], acc[mt][nt][3]);
            }
        }
    }
    __syncthreads();

    if (tid < 128) {
        int qg = q0 + tid;
        int gidx = b * NQ + qg;
        float r = g_rstd1[gidx];
        float mterm = r * g_mean1[gidx];
        float vals[48];
#pragma unroll
        for (int j = 0; j < 48; j++)
            vals[j] = r * Out[tid][j] - mterm * g_gs48[j] + g_c48[j] + g_qp[qg * 48 + j];

        float wpix = (float)(qg & 63);
        float hpix = (float)(qg >> 6);
#pragma unroll
        for (int h = 0; h < NHh; h++) {
            float* av = &vals[32 + h * 4];
            float mx = fmaxf(fmaxf(av[0], av[1]), fmaxf(av[2], av[3]));
            float e0 = __expf(av[0] - mx), e1 = __expf(av[1] - mx);
            float e2 = __expf(av[2] - mx), e3 = __expf(av[3] - mx);
            float inv = 1.0f / (e0 + e1 + e2 + e3);
            float aw[4] = {e0 * inv, e1 * inv, e2 * inv, e3 * inv};

            uint2* pp = g_pairs + ((size_t)gidx * 4 + h) * 16;
#pragma unroll
            for (int p = 0; p < NPp; p++) {
                float px = wpix + vals[h * 8 + p * 2];
                float py = hpix + vals[h * 8 + p * 2 + 1];
                float fx = floorf(px), fy = floorf(py);
                int ix = (int)fx, iy = (int)fy;
                float wx = px - fx, wy = py - fy;
                float a = aw[p];
                uint4 st0, st1;
#pragma unroll
                for (int c = 0; c < 4; c++) {
                    int cx = ix + (c & 1);
                    int cy = iy + (c >> 1);
                    bool valid = (cx >= 0) & (cx < Ww) & (cy >= 0) & (cy < Hh);
                    float wgt = valid ? ((c & 1) ? wx : 1.f - wx) * ((c >> 1) ? wy : 1.f - wy) * a : 0.f;
                    uint32_t off = valid ? (uint32_t)(cy * Ww + cx) * 512u : 0u;
                    if (c == 0) { st0.x = off; st0.y = __float_as_uint(wgt); }
                    if (c == 1) { st0.z = off; st0.w = __float_as_uint(wgt); }
                    if (c == 2) { st1.x = off; st1.y = __float_as_uint(wgt); }
                    if (c == 3) { st1.z = off; st1.w = __float_as_uint(wgt); }
                }
                *(uint4*)&pp[p * 4]     = st0;
                *(uint4*)&pp[p * 4 + 2] = st1;
            }
        }
    }
}

// ---------------- K4: value GEMM (bf16 mma, cp.async double-buffered) ----------------
__global__ void __launch_bounds__(256, 2) k_gemm_val()
{
    __shared__ uint32_t As2[2][16][136];
    __shared__ uint32_t Bs2[2][16][136];

    int b = blockIdx.z;
    int n0 = blockIdx.x * 128;
    int m0 = blockIdx.y * 128;
    int tid = threadIdx.x;
    int wid = tid >> 5, lane = tid & 31;
    int warp_m = wid & 1, warp_n = wid >> 1;
    int lr = lane >> 2, lk = lane & 3;

    float acc[4][4][4];
#pragma unroll
    for (int i = 0; i < 4; i++)
#pragma unroll
        for (int j = 0; j < 4; j++)
#pragma unroll
            for (int r = 0; r < 4; r++) acc[i][j][r] = 0.f;

    const uint32_t* Ab = g_x2b + (size_t)(b * 128) * NQ + m0;

    int row0 = tid >> 5, seg0 = tid & 31;
    int row1 = (tid + 256) >> 5, seg1 = (tid + 256) & 31;

    // prologue: tile 0
    cp16(&As2[0][row0][seg0 * 4], Ab + (size_t)row0 * NQ + seg0 * 4);
    cp16(&As2[0][row1][seg1 * 4], Ab + (size_t)row1 * NQ + seg1 * 4);
    cp16(&Bs2[0][row0][seg0 * 4], g_Wvb + row0 * 256 + n0 + seg0 * 4);
    cp16(&Bs2[0][row1][seg1 * 4], g_Wvb + row1 * 256 + n0 + seg1 * 4);
    CP_COMMIT();

    for (int it = 0; it < 8; it++) {
        if (it < 7) {
            int k2b = (it + 1) * 16;
            int s = (it + 1) & 1;
            cp16(&As2[s][row0][seg0 * 4], Ab + (size_t)(k2b + row0) * NQ + seg0 * 4);
            cp16(&As2[s][row1][seg1 * 4], Ab + (size_t)(k2b + row1) * NQ + seg1 * 4);
            cp16(&Bs2[s][row0][seg0 * 4], g_Wvb + (k2b + row0) * 256 + n0 + seg0 * 4);
            cp16(&Bs2[s][row1][seg1 * 4], g_Wvb + (k2b + row1) * 256 + n0 + seg1 * 4);
            CP_COMMIT();
            CP_WAIT1();
        } else {
            CP_WAIT0();
        }
        __syncthreads();
        int s = it & 1;
#pragma unroll
        for (int kk = 0; kk < 2; kk++) {
            int base = kk * 8;
            uint32_t a[4][4], bf[4][2];
#pragma unroll
            for (int mt = 0; mt < 4; mt++) {
                int r = warp_m * 64 + mt * 16 + lr;
                a[mt][0] = As2[s][base + lk][r];
                a[mt][1] = As2[s][base + lk][r + 8];
                a[mt][2] = As2[s][base + lk + 4][r];
                a[mt][3] = As2[s][base + lk + 4][r + 8];
            }
#pragma unroll
            for (int nt = 0; nt < 4; nt++) {
                int c = warp_n * 32 + nt * 8 + lr;
                bf[nt][0] = Bs2[s][base + lk][c];
                bf[nt][1] = Bs2[s][base + lk + 4][c];
            }
#pragma unroll
            for (int mt = 0; mt < 4; mt++)
#pragma unroll
                for (int nt = 0; nt < 4; nt++)
                    mma_bf16(acc[mt][nt], a[mt], bf[nt]);
        }
        __syncthreads();
    }

    int lc2 = (lane & 3) * 2;
#pragma unroll
    for (int mt = 0; mt < 4; mt++) {
        int q1 = m0 + warp_m * 64 + mt * 16 + lr;
        int q2 = q1 + 8;
        int g1 = b * NQ + q1, g2 = b * NQ + q2;
        float r1 = g_rstd2[g1], mm1 = r1 * g_mean2[g1];
        float r2 = g_rstd2[g2], mm2 = r2 * g_mean2[g2];
#pragma unroll
        for (int nt = 0; nt < 4; nt++) {
            int c = n0 + warp_n * 32 + nt * 8 + lc2;
            float vG0 = g_vG[c], vG1 = g_vG[c + 1];
            float vc0 = g_vc[c], vc1 = g_vc[c + 1];
            g_value[(size_t)g1 * 128 + (c >> 1)] =
                packbf(r1 * acc[mt][nt][0] - mm1 * vG0 + vc0,
                       r1 * acc[mt][nt][1] - mm1 * vG1 + vc1);
            g_value[(size_t)g2 * 128 + (c >> 1)] =
                packbf(r2 * acc[mt][nt][2] - mm2 * vG0 + vc0,
                       r2 * acc[mt][nt][3] - mm2 * vG1 + vc1);
        }
    }
}

// ---------------- K5: bilinear sampling — warp covers (q, 2 heads), lane = 4 channels ----------------
__global__ void __launch_bounds__(512) k_sample()
{
    int tid = threadIdx.x;
    int warp = tid >> 5, lane = tid & 31;
    int b = blockIdx.y;
    int qg = blockIdx.x * 8 + (warp >> 1);
    int hl = (warp & 1) * 2 + (lane >> 4);
    int sub = lane & 15;

    const uint2* __restrict__ pp = g_pairs + ((size_t)(b * NQ + qg) * 4 + hl) * 16;
    uint2 pr = pp[sub];

    const char* __restrict__ vbase =
        (const char*)g_value + (size_t)b * NQ * 512 + hl * 128 + sub * 8;

    float a0 = 0.f, a1 = 0.f, a2 = 0.f, a3 = 0.f;
#pragma unroll
    for (int c = 0; c < 16; c++) {
        uint32_t ob = __shfl_sync(0xFFFFFFFFu, pr.x, c, 16);
        float w = __uint_as_float(__shfl_sync(0xFFFFFFFFu, pr.y, c, 16));
        uint2 v = *(const uint2*)(vbase + ob);
        float v0 = __uint_as_float(v.x << 16);
        float v1 = __uint_as_float(v.x & 0xFFFF0000u);
        float v2 = __uint_as_float(v.y << 16);
        float v3 = __uint_as_float(v.y & 0xFFFF0000u);
        a0 += w * v0; a1 += w * v1; a2 += w * v2; a3 += w * v3;
    }
    uint2 st;
    st.x = packbf(a0, a1);
    st.y = packbf(a2, a3);
    *(uint2*)((char*)g_S + (size_t)(b * NQ + qg) * 512 + hl * 128 + sub * 8) = st;
}

// ---------------- K6: output GEMM (bf16 mma, A cp.async + B reg-pipelined) ----------------
__global__ void __launch_bounds__(256, 2) k_gemm_out(const float* __restrict__ x2,
                                                     const float* __restrict__ b_out,
                                                     float* __restrict__ out)
{
    __shared__ uint32_t As2[2][16][136];
    __shared__ uint32_t Bs2[2][16][136];

    int b = blockIdx.z;
    int m0 = blockIdx.x * 128;      // c'
    int n0 = blockIdx.y * 128;      // q
    int tid = threadIdx.x;
    int wid = tid >> 5, lane = tid & 31;
    int warp_m = wid & 1, warp_n = wid >> 1;
    int lr = lane >> 2, lk = lane & 3;

    float acc[4][4][4];
#pragma unroll
    for (int i = 0; i < 4; i++)
#pragma unroll
        for (int j = 0; j < 4; j++)
#pragma unroll
            for (int r = 0; r < 4; r++) acc[i][j][r] = 0.f;

    const uint32_t* Sb = g_S + (size_t)(b * NQ + n0) * 128;

    int row0 = tid >> 5, seg0 = tid & 31;
    int row1 = (tid + 256) >> 5, seg1 = (tid + 256) & 31;
    int bq = tid >> 4, bk = tid & 15;     // B: this thread's 8 (q, k2) slots

    uint32_t breg[8];

    // prologue tile 0
    cp16(&As2[0][row0][seg0 * 4], g_Wob + row0 * 256 + m0 + seg0 * 4);
    cp16(&As2[0][row1][seg1 * 4], g_Wob + row1 * 256 + m0 + seg1 * 4);
    CP_COMMIT();
#pragma unroll
    for (int i = 0; i < 8; i++)
        breg[i] = Sb[(size_t)(bq + i * 16) * 128 + bk];
#pragma unroll
    for (int i = 0; i < 8; i++)
        Bs2[0][bk][bq + i * 16] = breg[i];

    for (int it = 0; it < 8; it++) {
        if (it < 7) {
            int k2b = (it + 1) * 16;
            int s = (it + 1) & 1;
            cp16(&As2[s][row0][seg0 * 4], g_Wob + (k2b + row0) * 256 + m0 + seg0 * 4);
            cp16(&As2[s][row1][seg1 * 4], g_Wob + (k2b + row1) * 256 + m0 + seg1 * 4);
            CP_COMMIT();
#pragma unroll
            for (int i = 0; i < 8; i++)
                breg[i] = Sb[(size_t)(bq + i * 16) * 128 + k2b + bk];
            CP_WAIT1();
        } else {
            CP_WAIT0();
        }
        __syncthreads();
        int s = it & 1;
#pragma unroll
        for (int kk = 0; kk < 2; kk++) {
            int base = kk * 8;
            uint32_t a[4][4], bf[4][2];
#pragma unroll
            for (int mt = 0; mt < 4; mt++) {
                int r = warp_m * 64 + mt * 16 + lr;
                a[mt][0] = As2[s][base + lk][r];
                a[mt][1] = As2[s][base + lk][r + 8];
                a[mt][2] = As2[s][base + lk + 4][r];
                a[mt][3] = As2[s][base + lk + 4][r + 8];
            }
#pragma unroll
            for (int nt = 0; nt < 4; nt++) {
                int c = warp_n * 32 + nt * 8 + lr;
                bf[nt][0] = Bs2[s][base + lk][c];
                bf[nt][1] = Bs2[s][base + lk + 4][c];
            }
#pragma unroll
            for (int mt = 0; mt < 4; mt++)
#pragma unroll
                for (int nt = 0; nt < 4; nt++)
                    mma_bf16(acc[mt][nt], a[mt], bf[nt]);
        }
        if (it < 7) {
            int s2 = (it + 1) & 1;
#pragma unroll
            for (int i = 0; i < 8; i++)
                Bs2[s2][bk][bq + i * 16] = breg[i];
        }
        __syncthreads();
    }

    int lc2 = (lane & 3) * 2;
#pragma unroll
    for (int mt = 0; mt < 4; mt++) {
        int c1 = m0 + warp_m * 64 + mt * 16 + lr;
        int c2 = c1 + 8;
        float bo1 = b_out[c1], bo2 = b_out[c2];
        size_t base1 = ((size_t)b * Cc + c1) * NQ;
        size_t base2 = ((size_t)b * Cc + c2) * NQ;
#pragma unroll
        for (int nt = 0; nt < 4; nt++) {
            int q = n0 + warp_n * 32 + nt * 8 + lc2;
            float2 x1v = *(const float2*)(x2 + base1 + q);
            float2 x2v = *(const float2*)(x2 + base2 + q);
            float2 o1, o2;
            o1.x = acc[mt][nt][0] + bo1 + x1v.x;
            o1.y = acc[mt][nt][1] + bo1 + x1v.y;
            o2.x = acc[mt][nt][2] + bo2 + x2v.x;
            o2.y = acc[mt][nt][3] + bo2 + x2v.y;
            *(float2*)(out + base1 + q) = o1;
            *(float2*)(out + base2 + q) = o2;
        }
    }
}

// ---------------- launch ----------------
extern "C" void kernel_launch(void* const* d_in, const int* in_sizes, int n_in,
                              void* d_out, int out_size)
{
    const float* x1        = (const float*)d_in[0];
    const float* x2        = (const float*)d_in[1];
    const float* ln1_g     = (const float*)d_in[2];
    const float* ln1_b     = (const float*)d_in[3];
    const float* ln2_g     = (const float*)d_in[4];
    const float* ln2_b     = (const float*)d_in[5];
    const float* pos_scale = (const float*)d_in[6];
    const float* W_off     = (const float*)d_in[7];
    const float* b_off     = (const float*)d_in[8];
    const float* W_att     = (const float*)d_in[9];
    const float* b_att     = (const float*)d_in[10];
    const float* W_val     = (const float*)d_in[11];
    const float* b_val     = (const float*)d_in[12];
    const float* W_out     = (const float*)d_in[13];
    const float* b_out     = (const float*)d_in[14];
    float* out = (float*)d_out;

    k_pre<<<4362, 256>>>(x1, x2, ln1_g, ln1_b, ln2_g, ln2_b, pos_scale,
                         W_off, b_off, W_att, b_att, W_val, b_val, W_out);
    k_offatt<<<dim3(NQ / 128, Bb), 256>>>(x1);
    k_gemm_val<<<dim3(Cc / 128, NQ / 128, Bb), 256>>>();
    k_sample<<<dim3(NQ / 8, Bb), 512>>>();
    k_gemm_out<<<dim3(Cc / 128, NQ / 128, Bb), 256>>>(x2, b_out, out);
}

// round 7
// speedup vs baseline: 3.0700x; 1.0536x over previous
#include <cuda_runtime.h>
#include <cuda_bf16.h>
#include <math.h>
#include <stdint.h>

// Problem constants
#define Bb   8
#define Cc   256
#define Hh   64
#define Ww   64
#define NQ   4096           // H*W
#define NPIX (Bb*NQ)        // 32768
#define NHh  4
#define NPp  4
#define Dd   64
#define EPSf 1e-5f

// ---------------- scratch (static device globals; no allocation) ----------------
__device__ float g_mean1[NPIX], g_rstd1[NPIX], g_mean2[NPIX], g_rstd2[NPIX];
__device__ float g_qp[NQ * 48];          // qpos @ [W_off | W_att]
__device__ float g_c48[48];              // b + ln1_b @ W
__device__ float g_gs48[48];             // ln1_g @ W
__device__ float g_vG[Cc];               // ln2_g @ W_val
__device__ float g_vc[Cc];               // b_val + ln2_b @ W_val
__device__ uint32_t g_x1b[(size_t)NPIX * 128];  // bf16x2 pack of x1: [b][k2][q]
__device__ uint32_t g_x2b[(size_t)NPIX * 128];  // bf16x2 pack of x2: [b][k2][q]
__device__ uint32_t g_Wvb[128 * 256];    // bf16x2 (ln2_g-scaled W_val): [k2][n]
__device__ uint32_t g_Wob[128 * 256];    // bf16x2 W_out: [k2][m]
__device__ uint32_t g_Wqb[128 * 64];     // bf16x2 (ln1_g-scaled [W_off|W_att|0]): [k2][j]
__device__ uint32_t g_value[NPIX * Cc / 2];  // bf16x2: (B,Nq,C), pair (c, c+1)
__device__ uint2 g_pairs[(size_t)NPIX * 64]; // per (b,q,h): 16 x (byte offset, weight)
__device__ uint32_t g_S[NPIX * Cc / 2];      // bf16x2 sampled output (B,Nq,C)

// ---------------- helpers ----------------
__device__ __forceinline__ uint32_t packbf(float lo, float hi)
{
    __nv_bfloat162 h = __floats2bfloat162_rn(lo, hi);
    return *(uint32_t*)&h;
}

__device__ __forceinline__ void mma_bf16(float* d, const uint32_t* a, const uint32_t* b)
{
    asm volatile(
        "mma.sync.aligned.m16n8k16.row.col.f32.bf16.bf16.f32 "
        "{%0,%1,%2,%3}, {%4,%5,%6,%7}, {%8,%9}, {%0,%1,%2,%3};\n"
        : "+f"(d[0]), "+f"(d[1]), "+f"(d[2]), "+f"(d[3])
        : "r"(a[0]), "r"(a[1]), "r"(a[2]), "r"(a[3]), "r"(b[0]), "r"(b[1]));
}

__device__ __forceinline__ void cp16(void* smem_dst, const void* gmem_src)
{
    uint32_t sa = (uint32_t)__cvta_generic_to_shared(smem_dst);
    asm volatile("cp.async.cg.shared.global [%0], [%1], 16;\n" :: "r"(sa), "l"(gmem_src));
}
#define CP_COMMIT() asm volatile("cp.async.commit_group;\n" ::: "memory")
#define CP_WAIT1()  asm volatile("cp.async.wait_group 1;\n" ::: "memory")
#define CP_WAIT0()  asm volatile("cp.async.wait_group 0;\n" ::: "memory")

// ---------------- K_pre: const + stats/pack + qpos + weight packs, one launch ----------------
__global__ void __launch_bounds__(256) k_pre(
    const float* __restrict__ x1, const float* __restrict__ x2,
    const float* __restrict__ ln1_g, const float* __restrict__ ln1_b,
    const float* __restrict__ ln2_g, const float* __restrict__ ln2_b,
    const float* __restrict__ pos_scale,
    const float* __restrict__ W_off, const float* __restrict__ b_off,
    const float* __restrict__ W_att, const float* __restrict__ b_att,
    const float* __restrict__ W_val, const float* __restrict__ b_val,
    const float* __restrict__ W_out)
{
    int bid = blockIdx.x;
    int tid = threadIdx.x;

    if (bid == 0) {
        float sG = 0.f, sc = 0.f;
        for (int k = 0; k < Cc; k++) {
            float w = W_val[k * Cc + tid];
            sG += ln2_g[k] * w;
            sc += ln2_b[k] * w;
        }
        g_vG[tid] = sG;
        g_vc[tid] = sc + b_val[tid];

        if (tid < 48) {
            float s1 = 0.f, s2 = 0.f, bb;
            if (tid < 32) {
                for (int k = 0; k < Cc; k++) {
                    float w = W_off[k * 32 + tid];
                    s1 += ln1_b[k] * w;
                    s2 += ln1_g[k] * w;
                }
                bb = b_off[tid];
            } else {
                int j = tid - 32;
                for (int k = 0; k < Cc; k++) {
                    float w = W_att[k * 16 + j];
                    s1 += ln1_b[k] * w;
                    s2 += ln1_g[k] * w;
                }
                bb = b_att[j];
            }
            g_c48[tid] = s1 + bb;
            g_gs48[tid] = s2;
        }
    } else if (bid <= 256) {
        int t = (bid - 1) * 256 + tid;          // 0 .. 2*NPIX-1
        int idx = t & (NPIX - 1);
        int b = idx >> 12, q = idx & (NQ - 1);
        const float* p = ((t < NPIX) ? x1 : x2) + b * (Cc * NQ) + q;
        uint32_t* xb = ((t < NPIX) ? g_x1b : g_x2b) + (size_t)(b * 128) * NQ + q;
        float s = 0.f, ss = 0.f;
#pragma unroll 4
        for (int k2 = 0; k2 < 128; k2++) {
            float v0 = p[(2 * k2) * NQ];
            float v1 = p[(2 * k2 + 1) * NQ];
            s += v0 + v1;
            ss += v0 * v0 + v1 * v1;
            xb[(size_t)k2 * NQ] = packbf(v0, v1);
        }
        float m = s * (1.0f / Cc);
        float var = ss * (1.0f / Cc) - m * m;
        float r = rsqrtf(var + EPSf);
        if (t < NPIX) { g_mean1[idx] = m; g_rstd1[idx] = r; }
        else          { g_mean2[idx] = m; g_rstd2[idx] = r; }
    } else if (bid <= 4352) {
        __shared__ float qp[Cc];
        int q = bid - 257;
        float ps = pos_scale[0];
        {
            int k = tid;
            int i = (k < 128) ? k : k - 128;
            float invf = expf(-9.210340371976184f * (float)i * (1.0f / 128.0f));
            float ang = (float)q * invf;
            qp[k] = ((k < 128) ? sinf(ang) : cosf(ang)) * ps;
        }
        __syncthreads();
        if (tid < 192) {
            int j = tid >> 2;
            int part = tid & 3;
            float s = 0.f;
            int kk0 = part * 64;
            if (j < 32) {
                for (int k = kk0; k < kk0 + 64; k++) s += qp[k] * W_off[k * 32 + j];
            } else {
                int jj = j - 32;
                for (int k = kk0; k < kk0 + 64; k++) s += qp[k] * W_att[k * 16 + jj];
            }
            s += __shfl_xor_sync(0xFFFFFFFFu, s, 1);
            s += __shfl_xor_sync(0xFFFFFFFFu, s, 2);
            if (part == 0) g_qp[q * 48 + j] = s;
        }
    } else if (bid <= 4360) {
        int wb = bid - 4353;                    // 0..7
        if (wb < 4) {
#pragma unroll 4
            for (int r = 0; r < 32; r++) {
                int k2 = wb * 32 + r;
                int k = 2 * k2;
                float g0 = ln2_g[k], g1 = ln2_g[k + 1];
                g_Wvb[k2 * 256 + tid] = packbf(W_val[k * 256 + tid] * g0,
                                               W_val[(k + 1) * 256 + tid] * g1);
            }
        } else {
#pragma unroll 4
            for (int r = 0; r < 32; r++) {
                int k2 = (wb - 4) * 32 + r;
                int k = 2 * k2;
                g_Wob[k2 * 256 + tid] = packbf(W_out[k * 256 + tid],
                                               W_out[(k + 1) * 256 + tid]);
            }
        }
    } else {
#pragma unroll 4
        for (int i = 0; i < 32; i++) {
            int lin = i * 256 + tid;            // 8192
            int k2 = lin >> 6, j = lin & 63;
            int k = 2 * k2;
            float lo = 0.f, hi = 0.f;
            if (j < 32) {
                lo = W_off[k * 32 + j] * ln1_g[k];
                hi = W_off[(k + 1) * 32 + j] * ln1_g[k + 1];
            } else if (j < 48) {
                int jj = j - 32;
                lo = W_att[k * 16 + jj] * ln1_g[k];
                hi = W_att[(k + 1) * 16 + jj] * ln1_g[k + 1];
            }
            g_Wqb[k2 * 64 + j] = packbf(lo, hi);
        }
    }
}

// ---------------- K_mid: merged value-GEMM (bids 0..511) + off/att GEMM (bids 512..767) ----------------
union SmemMid {
    struct { uint32_t A[2][16][136]; uint32_t B[2][16][136]; } val;
    struct {
        union {
            struct { uint32_t A[16][136]; uint32_t Bq[16][72]; } p1;
            float Out[128][52];
        } u;
    } off;
};

__global__ void __launch_bounds__(256, 2) k_mid()
{
    __shared__ SmemMid sm;
    int bid = blockIdx.x;
    int tid = threadIdx.x;
    int wid = tid >> 5, lane = tid & 31;
    int lr = lane >> 2, lk = lane & 3;

    if (bid < 512) {
        // ======== value GEMM (cp.async double-buffered) ========
        int v = bid;
        int b = v >> 6;
        int m0 = ((v >> 1) & 31) * 128;
        int n0 = (v & 1) * 128;
        int warp_m = wid & 1, warp_n = wid >> 1;

        float acc[4][4][4];
#pragma unroll
        for (int i = 0; i < 4; i++)
#pragma unroll
            for (int j = 0; j < 4; j++)
#pragma unroll
                for (int r = 0; r < 4; r++) acc[i][j][r] = 0.f;

        const uint32_t* Ab = g_x2b + (size_t)(b * 128) * NQ + m0;

        int row0 = tid >> 5, seg0 = tid & 31;
        int row1 = (tid + 256) >> 5, seg1 = (tid + 256) & 31;

        cp16(&sm.val.A[0][row0][seg0 * 4], Ab + (size_t)row0 * NQ + seg0 * 4);
        cp16(&sm.val.A[0][row1][seg1 * 4], Ab + (size_t)row1 * NQ + seg1 * 4);
        cp16(&sm.val.B[0][row0][seg0 * 4], g_Wvb + row0 * 256 + n0 + seg0 * 4);
        cp16(&sm.val.B[0][row1][seg1 * 4], g_Wvb + row1 * 256 + n0 + seg1 * 4);
        CP_COMMIT();

        for (int it = 0; it < 8; it++) {
            if (it < 7) {
                int k2b = (it + 1) * 16;
                int s = (it + 1) & 1;
                cp16(&sm.val.A[s][row0][seg0 * 4], Ab + (size_t)(k2b + row0) * NQ + seg0 * 4);
                cp16(&sm.val.A[s][row1][seg1 * 4], Ab + (size_t)(k2b + row1) * NQ + seg1 * 4);
                cp16(&sm.val.B[s][row0][seg0 * 4], g_Wvb + (k2b + row0) * 256 + n0 + seg0 * 4);
                cp16(&sm.val.B[s][row1][seg1 * 4], g_Wvb + (k2b + row1) * 256 + n0 + seg1 * 4);
                CP_COMMIT();
                CP_WAIT1();
            } else {
                CP_WAIT0();
            }
            __syncthreads();
            int s = it & 1;
#pragma unroll
            for (int kk = 0; kk < 2; kk++) {
                int base = kk * 8;
                uint32_t a[4][4], bf[4][2];
#pragma unroll
                for (int mt = 0; mt < 4; mt++) {
                    int r = warp_m * 64 + mt * 16 + lr;
                    a[mt][0] = sm.val.A[s][base + lk][r];
                    a[mt][1] = sm.val.A[s][base + lk][r + 8];
                    a[mt][2] = sm.val.A[s][base + lk + 4][r];
                    a[mt][3] = sm.val.A[s][base + lk + 4][r + 8];
                }
#pragma unroll
                for (int nt = 0; nt < 4; nt++) {
                    int c = warp_n * 32 + nt * 8 + lr;
                    bf[nt][0] = sm.val.B[s][base + lk][c];
                    bf[nt][1] = sm.val.B[s][base + lk + 4][c];
                }
#pragma unroll
                for (int mt = 0; mt < 4; mt++)
#pragma unroll
                    for (int nt = 0; nt < 4; nt++)
                        mma_bf16(acc[mt][nt], a[mt], bf[nt]);
            }
            __syncthreads();
        }

        int lc2 = (lane & 3) * 2;
#pragma unroll
        for (int mt = 0; mt < 4; mt++) {
            int q1 = m0 + warp_m * 64 + mt * 16 + lr;
            int q2 = q1 + 8;
            int g1 = b * NQ + q1, g2 = b * NQ + q2;
            float r1 = g_rstd2[g1], mm1 = r1 * g_mean2[g1];
            float r2 = g_rstd2[g2], mm2 = r2 * g_mean2[g2];
#pragma unroll
            for (int nt = 0; nt < 4; nt++) {
                int c = n0 + (wid >> 1) * 32 + nt * 8 + lc2;
                float vG0 = g_vG[c], vG1 = g_vG[c + 1];
                float vc0 = g_vc[c], vc1 = g_vc[c + 1];
                g_value[(size_t)g1 * 128 + (c >> 1)] =
                    packbf(r1 * acc[mt][nt][0] - mm1 * vG0 + vc0,
                           r1 * acc[mt][nt][1] - mm1 * vG1 + vc1);
                g_value[(size_t)g2 * 128 + (c >> 1)] =
                    packbf(r2 * acc[mt][nt][2] - mm2 * vG0 + vc0,
                           r2 * acc[mt][nt][3] - mm2 * vG1 + vc1);
            }
        }
    } else {
        // ======== off/att GEMM + softmax + pair precompute ========
        int o = bid - 512;
        int b = o >> 5;
        int q0 = (o & 31) * 128;
        int warp_m = wid & 1, warp_n = wid >> 1;

        float acc[4][2][4];
#pragma unroll
        for (int i = 0; i < 4; i++)
#pragma unroll
            for (int j = 0; j < 2; j++)
#pragma unroll
                for (int r = 0; r < 4; r++) acc[i][j][r] = 0.f;

        const uint32_t* Ab = g_x1b + (size_t)(b * 128) * NQ + q0;

        for (int k0 = 0; k0 < Cc; k0 += 32) {
            int k2b = k0 >> 1;
#pragma unroll
            for (int i = 0; i < 2; i++) {
                int lin = tid + i * 256;
                int row = lin >> 5, seg = lin & 31;
                *(uint4*)&sm.off.u.p1.A[row][seg * 4] =
                    *(const uint4*)(Ab + (size_t)(k2b + row) * NQ + seg * 4);
            }
            {
                int row = tid >> 4, seg = tid & 15;
                *(uint4*)&sm.off.u.p1.Bq[row][seg * 4] =
                    *(const uint4*)(g_Wqb + (k2b + row) * 64 + seg * 4);
            }
            __syncthreads();
#pragma unroll
            for (int kk = 0; kk < 2; kk++) {
                int base = kk * 8;
                uint32_t a[4][4], bf[2][2];
#pragma unroll
                for (int mt = 0; mt < 4; mt++) {
                    int r = warp_m * 64 + mt * 16 + lr;
                    a[mt][0] = sm.off.u.p1.A[base + lk][r];
                    a[mt][1] = sm.off.u.p1.A[base + lk][r + 8];
                    a[mt][2] = sm.off.u.p1.A[base + lk + 4][r];
                    a[mt][3] = sm.off.u.p1.A[base + lk + 4][r + 8];
                }
#pragma unroll
                for (int nt = 0; nt < 2; nt++) {
                    int c = warp_n * 16 + nt * 8 + lr;
                    bf[nt][0] = sm.off.u.p1.Bq[base + lk][c];
                    bf[nt][1] = sm.off.u.p1.Bq[base + lk + 4][c];
                }
#pragma unroll
                for (int mt = 0; mt < 4; mt++)
#pragma unroll
                    for (int nt = 0; nt < 2; nt++)
                        mma_bf16(acc[mt][nt], a[mt], bf[nt]);
            }
            __syncthreads();
        }

        int lc2 = (lane & 3) * 2;
#pragma unroll
        for (int mt = 0; mt < 4; mt++) {
#pragma unroll
            for (int nt = 0; nt < 2; nt++) {
                int c = warp_n * 16 + nt * 8 + lc2;
                if (c < 48) {
                    int r = warp_m * 64 + mt * 16 + lr;
                    *(float2*)&sm.off.u.Out[r][c]     = make_float2(acc[mt][nt][0], acc[mt][nt][1]);
                    *(float2*)&sm.off.u.Out[r + 8][c] = make_float2(acc[mt][nt][2], acc[mt][nt][3]);
                }
            }
        }
        __syncthreads();

        if (tid < 128) {
            int qg = q0 + tid;
            int gidx = b * NQ + qg;
            float r = g_rstd1[gidx];
            float mterm = r * g_mean1[gidx];
            float vals[48];
#pragma unroll
            for (int j = 0; j < 48; j++)
                vals[j] = r * sm.off.u.Out[tid][j] - mterm * g_gs48[j] + g_c48[j] + g_qp[qg * 48 + j];

            float wpix = (float)(qg & 63);
            float hpix = (float)(qg >> 6);
#pragma unroll
            for (int h = 0; h < NHh; h++) {
                float* av = &vals[32 + h * 4];
                float mx = fmaxf(fmaxf(av[0], av[1]), fmaxf(av[2], av[3]));
                float e0 = __expf(av[0] - mx), e1 = __expf(av[1] - mx);
                float e2 = __expf(av[2] - mx), e3 = __expf(av[3] - mx);
                float inv = 1.0f / (e0 + e1 + e2 + e3);
                float aw[4] = {e0 * inv, e1 * inv, e2 * inv, e3 * inv};

                uint2* pp = g_pairs + ((size_t)gidx * 4 + h) * 16;
#pragma unroll
                for (int p = 0; p < NPp; p++) {
                    float px = wpix + vals[h * 8 + p * 2];
                    float py = hpix + vals[h * 8 + p * 2 + 1];
                    float fx = floorf(px), fy = floorf(py);
                    int ix = (int)fx, iy = (int)fy;
                    float wx = px - fx, wy = py - fy;
                    float a = aw[p];
                    uint4 st0, st1;
#pragma unroll
                    for (int c = 0; c < 4; c++) {
                        int cx = ix + (c & 1);
                        int cy = iy + (c >> 1);
                        bool valid = (cx >= 0) & (cx < Ww) & (cy >= 0) & (cy < Hh);
                        float wgt = valid ? ((c & 1) ? wx : 1.f - wx) * ((c >> 1) ? wy : 1.f - wy) * a : 0.f;
                        uint32_t off = valid ? (uint32_t)(cy * Ww + cx) * 512u : 0u;
                        if (c == 0) { st0.x = off; st0.y = __float_as_uint(wgt); }
                        if (c == 1) { st0.z = off; st0.w = __float_as_uint(wgt); }
                        if (c == 2) { st1.x = off; st1.y = __float_as_uint(wgt); }
                        if (c == 3) { st1.z = off; st1.w = __float_as_uint(wgt); }
                    }
                    *(uint4*)&pp[p * 4]     = st0;
                    *(uint4*)&pp[p * 4 + 2] = st1;
                }
            }
        }
    }
}

// ---------------- K5: bilinear sampling — warp = (q, 4 heads), lane = 8 channels ----------------
__global__ void __launch_bounds__(512) k_sample()
{
    int tid = threadIdx.x;
    int warp = tid >> 5, lane = tid & 31;
    int b = blockIdx.y;
    int qg = blockIdx.x * 16 + warp;
    int head = lane >> 3;
    int grp = lane & 7;
    int gidx = b * NQ + qg;

    // lane preloads pairs for corners (2*grp, 2*grp+1) of its head
    uint4 pr = *((const uint4*)(g_pairs + ((size_t)gidx * 4 + head) * 16) + grp);

    const char* __restrict__ vbase =
        (const char*)g_value + (size_t)b * NQ * 512 + head * 128 + grp * 16;

    float a0 = 0.f, a1 = 0.f, a2 = 0.f, a3 = 0.f;
    float a4 = 0.f, a5 = 0.f, a6 = 0.f, a7 = 0.f;
#pragma unroll
    for (int c = 0; c < 16; c++) {
        int srcl = c >> 1;
        uint32_t ob = __shfl_sync(0xFFFFFFFFu, (c & 1) ? pr.z : pr.x, srcl, 8);
        float w = __uint_as_float(__shfl_sync(0xFFFFFFFFu, (c & 1) ? pr.w : pr.y, srcl, 8));
        uint4 v = *(const uint4*)(vbase + ob);
        a0 += w * __uint_as_float(v.x << 16);
        a1 += w * __uint_as_float(v.x & 0xFFFF0000u);
        a2 += w * __uint_as_float(v.y << 16);
        a3 += w * __uint_as_float(v.y & 0xFFFF0000u);
        a4 += w * __uint_as_float(v.z << 16);
        a5 += w * __uint_as_float(v.z & 0xFFFF0000u);
        a6 += w * __uint_as_float(v.w << 16);
        a7 += w * __uint_as_float(v.w & 0xFFFF0000u);
    }
    uint4 st;
    st.x = packbf(a0, a1);
    st.y = packbf(a2, a3);
    st.z = packbf(a4, a5);
    st.w = packbf(a6, a7);
    *(uint4*)((char*)g_S + (size_t)gidx * 512 + head * 128 + grp * 16) = st;
}

// ---------------- K6: output GEMM (bf16 mma, A cp.async + B reg-pipelined) ----------------
__global__ void __launch_bounds__(256, 2) k_gemm_out(const float* __restrict__ x2,
                                                     const float* __restrict__ b_out,
                                                     float* __restrict__ out)
{
    __shared__ uint32_t As2[2][16][136];
    __shared__ uint32_t Bs2[2][16][136];

    int b = blockIdx.z;
    int m0 = blockIdx.x * 128;      // c'
    int n0 = blockIdx.y * 128;      // q
    int tid = threadIdx.x;
    int wid = tid >> 5, lane = tid & 31;
    int warp_m = wid & 1, warp_n = wid >> 1;
    int lr = lane >> 2, lk = lane & 3;

    float acc[4][4][4];
#pragma unroll
    for (int i = 0; i < 4; i++)
#pragma unroll
        for (int j = 0; j < 4; j++)
#pragma unroll
            for (int r = 0; r < 4; r++) acc[i][j][r] = 0.f;

    const uint32_t* Sb = g_S + (size_t)(b * NQ + n0) * 128;

    int row0 = tid >> 5, seg0 = tid & 31;
    int row1 = (tid + 256) >> 5, seg1 = (tid + 256) & 31;
    int bq = tid >> 4, bk = tid & 15;

    uint32_t breg[8];

    cp16(&As2[0][row0][seg0 * 4], g_Wob + row0 * 256 + m0 + seg0 * 4);
    cp16(&As2[0][row1][seg1 * 4], g_Wob + row1 * 256 + m0 + seg1 * 4);
    CP_COMMIT();
#pragma unroll
    for (int i = 0; i < 8; i++)
        breg[i] = Sb[(size_t)(bq + i * 16) * 128 + bk];
#pragma unroll
    for (int i = 0; i < 8; i++)
        Bs2[0][bk][bq + i * 16] = breg[i];

    for (int it = 0; it < 8; it++) {
        if (it < 7) {
            int k2b = (it + 1) * 16;
            int s = (it + 1) & 1;
            cp16(&As2[s][row0][seg0 * 4], g_Wob + (k2b + row0) * 256 + m0 + seg0 * 4);
            cp16(&As2[s][row1][seg1 * 4], g_Wob + (k2b + row1) * 256 + m0 + seg1 * 4);
            CP_COMMIT();
#pragma unroll
            for (int i = 0; i < 8; i++)
                breg[i] = Sb[(size_t)(bq + i * 16) * 128 + k2b + bk];
            CP_WAIT1();
        } else {
            CP_WAIT0();
        }
        __syncthreads();
        int s = it & 1;
#pragma unroll
        for (int kk = 0; kk < 2; kk++) {
            int base = kk * 8;
            uint32_t a[4][4], bf[4][2];
#pragma unroll
            for (int mt = 0; mt < 4; mt++) {
                int r = warp_m * 64 + mt * 16 + lr;
                a[mt][0] = As2[s][base + lk][r];
                a[mt][1] = As2[s][base + lk][r + 8];
                a[mt][2] = As2[s][base + lk + 4][r];
                a[mt][3] = As2[s][base + lk + 4][r + 8];
            }
#pragma unroll
            for (int nt = 0; nt < 4; nt++) {
                int c = warp_n * 32 + nt * 8 + lr;
                bf[nt][0] = Bs2[s][base + lk][c];
                bf[nt][1] = Bs2[s][base + lk + 4][c];
            }
#pragma unroll
            for (int mt = 0; mt < 4; mt++)
#pragma unroll
                for (int nt = 0; nt < 4; nt++)
                    mma_bf16(acc[mt][nt], a[mt], bf[nt]);
        }
        if (it < 7) {
            int s2 = (it + 1) & 1;
#pragma unroll
            for (int i = 0; i < 8; i++)
                Bs2[s2][bk][bq + i * 16] = breg[i];
        }
        __syncthreads();
    }

    int lc2 = (lane & 3) * 2;
#pragma unroll
    for (int mt = 0; mt < 4; mt++) {
        int c1 = m0 + warp_m * 64 + mt * 16 + lr;
        int c2 = c1 + 8;
        float bo1 = b_out[c1], bo2 = b_out[c2];
        size_t base1 = ((size_t)b * Cc + c1) * NQ;
        size_t base2 = ((size_t)b * Cc + c2) * NQ;
#pragma unroll
        for (int nt = 0; nt < 4; nt++) {
            int q = n0 + warp_n * 32 + nt * 8 + lc2;
            float2 x1v = *(const float2*)(x2 + base1 + q);
            float2 x2v = *(const float2*)(x2 + base2 + q);
            float2 o1, o2;
            o1.x = acc[mt][nt][0] + bo1 + x1v.x;
            o1.y = acc[mt][nt][1] + bo1 + x1v.y;
            o2.x = acc[mt][nt][2] + bo2 + x2v.x;
            o2.y = acc[mt][nt][3] + bo2 + x2v.y;
            *(float2*)(out + base1 + q) = o1;
            *(float2*)(out + base2 + q) = o2;
        }
    }
}

// ---------------- launch ----------------
extern "C" void kernel_launch(void* const* d_in, const int* in_sizes, int n_in,
                              void* d_out, int out_size)
{
    const float* x1        = (const float*)d_in[0];
    const float* x2        = (const float*)d_in[1];
    const float* ln1_g     = (const float*)d_in[2];
    const float* ln1_b     = (const float*)d_in[3];
    const float* ln2_g     = (const float*)d_in[4];
    const float* ln2_b     = (const float*)d_in[5];
    const float* pos_scale = (const float*)d_in[6];
    const float* W_off     = (const float*)d_in[7];
    const float* b_off     = (const float*)d_in[8];
    const float* W_att     = (const float*)d_in[9];
    const float* b_att     = (const float*)d_in[10];
    const float* W_val     = (const float*)d_in[11];
    const float* b_val     = (const float*)d_in[12];
    const float* W_out     = (const float*)d_in[13];
    const float* b_out     = (const float*)d_in[14];
    float* out = (float*)d_out;

    k_pre<<<4362, 256>>>(x1, x2, ln1_g, ln1_b, ln2_g, ln2_b, pos_scale,
                         W_off, b_off, W_att, b_att, W_val, b_val, W_out);
    k_mid<<<768, 256>>>();
    k_sample<<<dim3(NQ / 16, Bb), 512>>>();
    k_gemm_out<<<dim3(Cc / 128, NQ / 128, Bb), 256>>>(x2, b_out, out);
}